// round 2
// baseline (speedup 1.0000x reference)
#include <cuda_runtime.h>
#include <math.h>

// Problem shape (fixed by reference setup_inputs)
#define BATCH 8
#define TQ    2048
#define TK    2048
#define HD    1024

// Scratch for energy / softmax probabilities: 8*2048*2048 fp32 = 128 MiB
__device__ float g_energy[(size_t)BATCH * TQ * TK];

// ---------------------------------------------------------------------------
// SIMT fp32 GEMM, 128x128 block tile, 8x8 per thread, k-chunk 8, 256 threads.
// TRANSB=true : C[M,N] = A[M,K] * B[N,K]^T   (contract fastest dim of both)
// TRANSB=false: C[M,N] = A[M,K] * B[K,N]     (contract fastest dim of A only)
// All dims assumed multiples of 128 (they are: 2048/2048/1024).
// ---------------------------------------------------------------------------
template <bool TRANSB>
__global__ void __launch_bounds__(256, 2)
sgemm_kernel(const float* __restrict__ A,
             const float* __restrict__ Bm,
             float* __restrict__ C,
             int M, int N, int K)
{
    const size_t bA = (size_t)blockIdx.z * (size_t)M * K;
    const size_t bB = (size_t)blockIdx.z * (TRANSB ? (size_t)N * K : (size_t)K * N);
    const size_t bC = (size_t)blockIdx.z * (size_t)M * N;
    const float* Ab = A + bA;
    const float* Bb = Bm + bB;
    float* Cb = C + bC;

    __shared__ float As[8][128];
    __shared__ float Bs[8][128];

    const int tid = threadIdx.x;
    const int m0 = blockIdx.y * 128;
    const int n0 = blockIdx.x * 128;

    const int ty = tid >> 4;        // 0..15 -> C rows ty*8..ty*8+7
    const int tx = tid & 15;        // 0..15 -> C cols tx*8..tx*8+7

    // A-tile (and TRANSB B-tile) loader mapping: 128 rows x 8 k, float4 along k
    const int arow  = tid >> 1;       // 0..127
    const int acol4 = (tid & 1) * 4;  // 0 or 4

    // NN B-tile loader mapping: 8 k-rows x 128 n, float4 along n
    const int brow  = tid >> 5;       // 0..7
    const int bcol  = (tid & 31) * 4; // 0..124

    float acc[8][8];
#pragma unroll
    for (int i = 0; i < 8; i++)
#pragma unroll
        for (int j = 0; j < 8; j++) acc[i][j] = 0.0f;

    for (int kt = 0; kt < K; kt += 8) {
        // ---- global loads into registers
        float4 av = *(const float4*)(Ab + (size_t)(m0 + arow) * K + kt + acol4);
        float4 bv;
        if (TRANSB) {
            bv = *(const float4*)(Bb + (size_t)(n0 + arow) * K + kt + acol4);
        } else {
            bv = *(const float4*)(Bb + (size_t)(kt + brow) * N + n0 + bcol);
        }

        __syncthreads();   // previous iteration's smem reads done

        // ---- stage into smem (A transposed to [k][m])
        As[acol4 + 0][arow] = av.x;
        As[acol4 + 1][arow] = av.y;
        As[acol4 + 2][arow] = av.z;
        As[acol4 + 3][arow] = av.w;
        if (TRANSB) {
            Bs[acol4 + 0][arow] = bv.x;
            Bs[acol4 + 1][arow] = bv.y;
            Bs[acol4 + 2][arow] = bv.z;
            Bs[acol4 + 3][arow] = bv.w;
        } else {
            *(float4*)&Bs[brow][bcol] = bv;
        }

        __syncthreads();

        // ---- compute
#pragma unroll
        for (int kk = 0; kk < 8; kk++) {
            float a[8], b[8];
            *(float4*)&a[0] = *(const float4*)&As[kk][ty * 8];
            *(float4*)&a[4] = *(const float4*)&As[kk][ty * 8 + 4];
            *(float4*)&b[0] = *(const float4*)&Bs[kk][tx * 8];
            *(float4*)&b[4] = *(const float4*)&Bs[kk][tx * 8 + 4];
#pragma unroll
            for (int i = 0; i < 8; i++)
#pragma unroll
                for (int j = 0; j < 8; j++)
                    acc[i][j] = fmaf(a[i], b[j], acc[i][j]);
        }
    }

    // ---- epilogue
#pragma unroll
    for (int i = 0; i < 8; i++) {
        float* crow = Cb + (size_t)(m0 + ty * 8 + i) * N + n0 + tx * 8;
        *(float4*)&crow[0] = *(float4*)&acc[i][0];
        *(float4*)&crow[4] = *(float4*)&acc[i][4];
    }
}

// ---------------------------------------------------------------------------
// Row softmax over TK=2048 elements, in place. One 256-thread block per row.
// ---------------------------------------------------------------------------
__global__ void __launch_bounds__(256)
softmax_kernel(float* __restrict__ E)
{
    const size_t row = blockIdx.x;               // 0 .. BATCH*TQ-1
    float* e = E + row * (size_t)TK;
    const int tid = threadIdx.x;
    const int lane = tid & 31;
    const int warp = tid >> 5;

    __shared__ float red[32];

    float v[8];
    float m = -INFINITY;
#pragma unroll
    for (int i = 0; i < 8; i++) {
        v[i] = e[tid + i * 256];
        m = fmaxf(m, v[i]);
    }
    // block max
#pragma unroll
    for (int o = 16; o > 0; o >>= 1) m = fmaxf(m, __shfl_xor_sync(0xffffffffu, m, o));
    if (lane == 0) red[warp] = m;
    __syncthreads();
    if (warp == 0) {
        float t = red[lane & 7];
#pragma unroll
        for (int o = 4; o > 0; o >>= 1) t = fmaxf(t, __shfl_xor_sync(0xffffffffu, t, o));
        red[lane] = t;
    }
    __syncthreads();
    m = red[0];

    float s = 0.0f;
#pragma unroll
    for (int i = 0; i < 8; i++) {
        v[i] = __expf(v[i] - m);
        s += v[i];
    }
    // block sum
#pragma unroll
    for (int o = 16; o > 0; o >>= 1) s += __shfl_xor_sync(0xffffffffu, s, o);
    __syncthreads();
    if (lane == 0) red[warp] = s;
    __syncthreads();
    if (warp == 0) {
        float t = red[lane & 7];
#pragma unroll
        for (int o = 4; o > 0; o >>= 1) t += __shfl_xor_sync(0xffffffffu, t, o);
        red[lane] = t;
    }
    __syncthreads();
    const float inv = 1.0f / red[0];

#pragma unroll
    for (int i = 0; i < 8; i++) e[tid + i * 256] = v[i] * inv;
}

// ---------------------------------------------------------------------------
extern "C" void kernel_launch(void* const* d_in, const int* in_sizes, int n_in,
                              void* d_out, int out_size)
{
    const float* Q = (const float*)d_in[0];   // [B, TQ, HD]
    const float* Kt = (const float*)d_in[1];  // [B, TK, HD]
    float* O = (float*)d_out;                 // [B, TQ, HD]

    float* E = nullptr;
    cudaGetSymbolAddress((void**)&E, g_energy);

    // 1) E = Q @ K^T   (M=TQ, N=TK, K=HD), NT
    {
        dim3 grid(TK / 128, TQ / 128, BATCH);
        sgemm_kernel<true><<<grid, 256>>>(Q, Kt, E, TQ, TK, HD);
    }
    // 2) P = softmax(E) rows
    {
        softmax_kernel<<<BATCH * TQ, 256>>>(E);
    }
    // 3) O = P @ K     (M=TQ, N=HD, K=TK), NN
    {
        dim3 grid(HD / 128, TQ / 128, BATCH);
        sgemm_kernel<false><<<grid, 256>>>(E, Kt, O, TQ, HD, TK);
    }
    (void)in_sizes; (void)n_in; (void)out_size;
}

// round 4
// speedup vs baseline: 3.9948x; 3.9948x over previous
#include <cuda_runtime.h>
#include <cuda_bf16.h>
#include <cstdint>
#include <math.h>

#define BATCH 8
#define TQ    2048
#define TK    2048
#define HD    1024

#if defined(__CUDA_ARCH_FEAT_SM103_ALL) || defined(__CUDA_ARCH_FEAT_SM100_ALL)
#define HAS_TCGEN05 1
#else
#define HAS_TCGEN05 0
#endif

// ---------------------------------------------------------------------------
// Device scratch (allocation-free rule: __device__ globals)
// ---------------------------------------------------------------------------
__device__ float         g_E   [(size_t)BATCH * TQ * TK];
__device__ __nv_bfloat16 g_Qhi [(size_t)BATCH * TQ * HD];
__device__ __nv_bfloat16 g_Qlo [(size_t)BATCH * TQ * HD];
__device__ __nv_bfloat16 g_Khi [(size_t)BATCH * TK * HD];
__device__ __nv_bfloat16 g_Klo [(size_t)BATCH * TK * HD];
__device__ __nv_bfloat16 g_KThi[(size_t)BATCH * HD * TK];
__device__ __nv_bfloat16 g_KTlo[(size_t)BATCH * HD * TK];
__device__ __nv_bfloat16 g_Phi [(size_t)BATCH * TQ * TK];
__device__ __nv_bfloat16 g_Plo [(size_t)BATCH * TQ * TK];

// ---------------------------------------------------------------------------
// Common helpers
// ---------------------------------------------------------------------------
__device__ __forceinline__ uint32_t smem_u32(const void* p) {
    uint32_t a;
    asm("{ .reg .u64 t; cvta.to.shared.u64 t, %1; cvt.u32.u64 %0, t; }" : "=r"(a) : "l"(p));
    return a;
}

__device__ __forceinline__ void sts128(uint32_t addr, uint4 v) {
    asm volatile("st.shared.v4.b32 [%0], {%1,%2,%3,%4};"
                 :: "r"(addr), "r"(v.x), "r"(v.y), "r"(v.z), "r"(v.w) : "memory");
}

__device__ __forceinline__ void split_bf16(float x, __nv_bfloat16& h, __nv_bfloat16& l) {
    h = __float2bfloat16(x);
    l = __float2bfloat16(x - __bfloat162float(h));
}

// ---------------------------------------------------------------------------
// tcgen05 helpers (compiled only in the sm_103a/sm_100a pass)
// ---------------------------------------------------------------------------
#if HAS_TCGEN05
__device__ __forceinline__ uint32_t elect_one() {
    uint32_t p;
    asm volatile("{\n\t.reg .pred p;\n\telect.sync _|p, 0xFFFFFFFF;\n\tselp.b32 %0, 1, 0, p;\n\t}"
                 : "=r"(p));
    return p;
}

#define MBARRIER_INIT(addr, cnt) \
    asm volatile("mbarrier.init.shared.b64 [%0], %1;" :: "r"((uint32_t)(addr)), "r"((uint32_t)(cnt)) : "memory")

#define MBARRIER_WAIT_PARITY(addr, parity) do {                                              \
    uint32_t _m = (uint32_t)(addr); uint32_t _p = (uint32_t)(parity); uint32_t _d;            \
    asm volatile("{\n\t.reg .pred p;\n\t"                                                     \
        "mbarrier.try_wait.parity.acquire.cta.shared::cta.b64 p, [%1], %2;\n\t"               \
        "selp.b32 %0, 1, 0, p;\n\t}" : "=r"(_d) : "r"(_m), "r"(_p) : "memory");               \
    if (!_d) {                                                                                \
        asm volatile("{\n\t.reg .pred P1;\n\t"                                                \
            "WL_%=:\n\t"                                                                      \
            "mbarrier.try_wait.parity.acquire.cta.shared::cta.b64 P1, [%0], %1, 0x989680;\n\t"\
            "@P1 bra.uni WD_%=;\n\t"                                                          \
            "bra.uni WL_%=;\n\t"                                                              \
            "WD_%=:\n\t}" :: "r"(_m), "r"(_p) : "memory");                                    \
    }                                                                                         \
} while (0)

#define TCGEN05_ALLOC(smem_addr, ncols) \
    asm volatile("tcgen05.alloc.cta_group::1.sync.aligned.shared::cta.b32 [%0], %1;" \
                 :: "r"((uint32_t)(smem_addr)), "r"((uint32_t)(ncols)) : "memory")
#define TCGEN05_DEALLOC(tmem, ncols) \
    asm volatile("tcgen05.dealloc.cta_group::1.sync.aligned.b32 %0, %1;" :: "r"(tmem), "r"((uint32_t)(ncols)))
#define TCGEN05_COMMIT(mbar) \
    asm volatile("tcgen05.commit.cta_group::1.mbarrier::arrive::one.shared::cluster.b64 [%0];" \
                 :: "r"((uint32_t)(mbar)) : "memory")
#define TCGEN05_FENCE_AFTER()  asm volatile("tcgen05.fence::after_thread_sync;"  ::: "memory")
#define TCGEN05_FENCE_BEFORE() asm volatile("tcgen05.fence::before_thread_sync;" ::: "memory")
#define TCGEN05_WAIT_LD()      asm volatile("tcgen05.wait::ld.sync.aligned;"     ::: "memory")
#define FENCE_PROXY_ASYNC()    asm volatile("fence.proxy.async.shared::cta;"     ::: "memory")

#define TCGEN05_LD_32X32B_X32(r, tmem_addr) \
    asm volatile( \
        "tcgen05.ld.sync.aligned.32x32b.x32.b32 " \
        "{%0, %1, %2, %3, %4, %5, %6, %7, " \
        " %8, %9, %10, %11, %12, %13, %14, %15, " \
        " %16, %17, %18, %19, %20, %21, %22, %23, " \
        " %24, %25, %26, %27, %28, %29, %30, %31}, [%32];" \
        : "=r"((r)[0]),  "=r"((r)[1]),  "=r"((r)[2]),  "=r"((r)[3]), \
          "=r"((r)[4]),  "=r"((r)[5]),  "=r"((r)[6]),  "=r"((r)[7]), \
          "=r"((r)[8]),  "=r"((r)[9]),  "=r"((r)[10]), "=r"((r)[11]), \
          "=r"((r)[12]), "=r"((r)[13]), "=r"((r)[14]), "=r"((r)[15]), \
          "=r"((r)[16]), "=r"((r)[17]), "=r"((r)[18]), "=r"((r)[19]), \
          "=r"((r)[20]), "=r"((r)[21]), "=r"((r)[22]), "=r"((r)[23]), \
          "=r"((r)[24]), "=r"((r)[25]), "=r"((r)[26]), "=r"((r)[27]), \
          "=r"((r)[28]), "=r"((r)[29]), "=r"((r)[30]), "=r"((r)[31]) \
        : "r"(tmem_addr))

__device__ __forceinline__ void mma_f16_ss(uint32_t d, uint64_t ad, uint64_t bd,
                                           uint32_t idesc, bool acc) {
    uint32_t en = acc ? 1u : 0u;
    asm volatile(
        "{\n\t.reg .pred p;\n\tsetp.ne.u32 p, %5, 0;\n\t"
        "tcgen05.mma.cta_group::1.kind::f16 [%0], %1, %2, %3, {%4, %4, %4, %4}, p;\n\t}"
        :: "r"(d), "l"(ad), "l"(bd), "r"(idesc), "r"(0u), "r"(en) : "memory");
}

__device__ __forceinline__ uint64_t make_desc(uint32_t addr) {
    const uint64_t base = (2ULL << 61) | (1ULL << 46) | (64ULL << 32) | (1ULL << 16);
    return base | ((uint64_t)(addr >> 4) & 0x3FFF);
}
#define MMA_IDESC 0x8200490u
#endif  // HAS_TCGEN05

// ---------------------------------------------------------------------------
// HMMA fallback helpers (plain sm_103 / sm_80+)
// ---------------------------------------------------------------------------
__device__ __forceinline__ void ldsm4(uint32_t* r, uint32_t addr) {
    asm volatile("ldmatrix.sync.aligned.m8n8.x4.shared.b16 {%0,%1,%2,%3}, [%4];"
                 : "=r"(r[0]), "=r"(r[1]), "=r"(r[2]), "=r"(r[3]) : "r"(addr));
}

__device__ __forceinline__ void mma_bf16(float* d, const uint32_t* a, const uint32_t* b) {
    asm volatile(
        "mma.sync.aligned.m16n8k16.row.col.f32.bf16.bf16.f32 "
        "{%0,%1,%2,%3}, {%4,%5,%6,%7}, {%8,%9}, {%0,%1,%2,%3};"
        : "+f"(d[0]), "+f"(d[1]), "+f"(d[2]), "+f"(d[3])
        : "r"(a[0]), "r"(a[1]), "r"(a[2]), "r"(a[3]), "r"(b[0]), "r"(b[1]));
}

// ---------------------------------------------------------------------------
// Unified GEMM kernel: C[M,N] = (Ahi+Alo)[M,Kt] * (Bhi+Blo)[N,Kt]^T, fp32 out.
// Dims: M,N mult of 128; Ktot mult of 64.
// ---------------------------------------------------------------------------
#define SM_TMEMPTR 0
#define SM_MBAR0   8
#define SM_MBAR1   16
#define SM_BUF     1024
#define BUF_BYTES  65536
#define GEMM_SMEM  (SM_BUF + 2 * BUF_BYTES)

__global__ void __launch_bounds__(256, 1)
gemm_split_kernel(const __nv_bfloat16* __restrict__ Ahi, const __nv_bfloat16* __restrict__ Alo,
                  const __nv_bfloat16* __restrict__ Bhi, const __nv_bfloat16* __restrict__ Blo,
                  float* __restrict__ C, int M, int N, int Ktot)
{
#if HAS_TCGEN05
    // ===================== tcgen05 path =====================
    extern __shared__ char smem[];
    const uint32_t sb = smem_u32(smem);
    const int tid = threadIdx.x;
    const int wid = tid >> 5, lid = tid & 31;
    const int m0 = blockIdx.y * 128, n0 = blockIdx.x * 128;

    const size_t offA = (size_t)blockIdx.z * M * Ktot;
    const size_t offB = (size_t)blockIdx.z * N * Ktot;
    const __nv_bfloat16* pA[2] = { Ahi + offA, Alo + offA };
    const __nv_bfloat16* pB[2] = { Bhi + offB, Blo + offB };

    if (wid == 0) TCGEN05_ALLOC(sb + SM_TMEMPTR, 128);
    if (tid == 0) { MBARRIER_INIT(sb + SM_MBAR0, 1); MBARRIER_INIT(sb + SM_MBAR1, 1); }
    __syncthreads();
    uint32_t tmem;
    asm volatile("ld.shared.b32 %0, [%1];" : "=r"(tmem) : "r"(sb + SM_TMEMPTR));

    const int nchunks = Ktot >> 6;
    int ph0 = 0, ph1 = 0;

    for (int c = 0; c < nchunks; c++) {
        const int buf = c & 1;
        const uint32_t bufbase = sb + SM_BUF + buf * BUF_BYTES;
        if (c >= 2) {
            if (buf == 0) { MBARRIER_WAIT_PARITY(sb + SM_MBAR0, ph0); ph0 ^= 1; }
            else          { MBARRIER_WAIT_PARITY(sb + SM_MBAR1, ph1); ph1 ^= 1; }
        }
        const int kt0 = c << 6;

#pragma unroll
        for (int s = 0; s < 4; s++) {
            const __nv_bfloat16* src = (s < 2) ? pA[s] : pB[s - 2];
            const int rbase = (s < 2) ? m0 : n0;
            const uint32_t dst = bufbase + s * 16384;
#pragma unroll
            for (int j = 0; j < 4; j++) {
                const int seg = tid + j * 256;
                const int row = seg >> 3, c16 = seg & 7;
                uint4 v = *(const uint4*)(src + (size_t)(rbase + row) * Ktot + kt0 + c16 * 8);
                uint32_t off = (uint32_t)(row * 128 + c16 * 16);
                uint32_t sw = off ^ ((off >> 3) & 0x70);
                sts128(dst + sw, v);
            }
        }
        __syncthreads();
        FENCE_PROXY_ASYNC();

        if (wid == 0 && elect_one()) {
            const uint64_t dAh = make_desc(bufbase + 0);
            const uint64_t dAl = make_desc(bufbase + 16384);
            const uint64_t dBh = make_desc(bufbase + 32768);
            const uint64_t dBl = make_desc(bufbase + 49152);
            const bool first = (c == 0);
#pragma unroll
            for (int s = 0; s < 4; s++)
                mma_f16_ss(tmem, dAh + s * 2, dBh + s * 2, MMA_IDESC, !(first && s == 0));
#pragma unroll
            for (int s = 0; s < 4; s++)
                mma_f16_ss(tmem, dAh + s * 2, dBl + s * 2, MMA_IDESC, true);
#pragma unroll
            for (int s = 0; s < 4; s++)
                mma_f16_ss(tmem, dAl + s * 2, dBh + s * 2, MMA_IDESC, true);
#pragma unroll
            for (int s = 0; s < 4; s++)
                mma_f16_ss(tmem, dAl + s * 2, dBl + s * 2, MMA_IDESC, true);
            TCGEN05_COMMIT(sb + (buf ? SM_MBAR1 : SM_MBAR0));
        }
    }

    MBARRIER_WAIT_PARITY(sb + SM_MBAR0, ph0);
    if (nchunks >= 2) { MBARRIER_WAIT_PARITY(sb + SM_MBAR1, ph1); }
    TCGEN05_FENCE_AFTER();

    {
        const int sub = wid & 3, half = wid >> 2;
        const int row = sub * 32 + lid;
        float* crow = C + (size_t)blockIdx.z * M * N + (size_t)(m0 + row) * N + n0 + half * 64;
#pragma unroll
        for (int g = 0; g < 2; g++) {
            uint32_t regs[32];
            TCGEN05_LD_32X32B_X32(regs, tmem + half * 64 + g * 32);
            TCGEN05_WAIT_LD();
#pragma unroll
            for (int q = 0; q < 8; q++) {
                float4 f;
                f.x = __uint_as_float(regs[q * 4 + 0]);
                f.y = __uint_as_float(regs[q * 4 + 1]);
                f.z = __uint_as_float(regs[q * 4 + 2]);
                f.w = __uint_as_float(regs[q * 4 + 3]);
                *(float4*)(crow + g * 32 + q * 4) = f;
            }
        }
    }
    TCGEN05_FENCE_BEFORE();
    __syncthreads();
    if (wid == 0) TCGEN05_DEALLOC(tmem, 128);

#else
    // ===================== HMMA (mma.sync) fallback =====================
    // 128x128 CTA tile, 8 warps in 2x4 -> 64x32 warp tile, KC=32 chunks.
    // smem: 4 matrices (Ahi,Alo,Bhi,Blo) of 128 rows x 32 bf16, pitch 80B.
    extern __shared__ char smem[];
    const uint32_t sb = smem_u32(smem);
    const int tid  = threadIdx.x;
    const int lane = tid & 31, wid = tid >> 5;
    const int wm = wid & 1, wn = wid >> 1;        // warp grid 2 (m) x 4 (n)
    const int m0 = blockIdx.y * 128, n0 = blockIdx.x * 128;

    const size_t offA = (size_t)blockIdx.z * M * Ktot;
    const size_t offB = (size_t)blockIdx.z * N * Ktot;
    const __nv_bfloat16* srcs[4] = { Ahi + offA, Alo + offA, Bhi + offB, Blo + offB };
    const int rb[4] = { m0, m0, n0, n0 };
    const uint32_t mats[4] = { sb, sb + 10240u, sb + 20480u, sb + 30720u };

    // ldmatrix per-lane base offsets (within a matrix, before mt/nt2/kb offsets)
    const uint32_t a_off = (uint32_t)((wm * 64 + (lane & 15)) * 80 + (lane >> 4) * 16);
    const uint32_t b_off = (uint32_t)((wn * 32 + ((lane >> 4) & 1) * 8 + (lane & 7)) * 80
                                      + ((lane >> 3) & 1) * 16);

    float acc[4][4][4];
#pragma unroll
    for (int i = 0; i < 4; i++)
#pragma unroll
        for (int j = 0; j < 4; j++)
#pragma unroll
            for (int q = 0; q < 4; q++) acc[i][j][q] = 0.0f;

    const int nchunks = Ktot >> 5;
    const int lr = tid >> 2, lq = tid & 3;   // loader: row quarter mapping
    uint4 st[4][2];

#pragma unroll 1
    for (int c = 0; c < nchunks; c++) {
        if (c == 0) {
#pragma unroll
            for (int s = 0; s < 4; s++)
#pragma unroll
                for (int j = 0; j < 2; j++)
                    st[s][j] = *(const uint4*)(srcs[s] + (size_t)(rb[s] + lr + j * 64) * Ktot + lq * 8);
        }
        __syncthreads();
#pragma unroll
        for (int s = 0; s < 4; s++)
#pragma unroll
            for (int j = 0; j < 2; j++)
                sts128(mats[s] + (uint32_t)((lr + j * 64) * 80 + lq * 16), st[s][j]);
        __syncthreads();

        if (c + 1 < nchunks) {
            const int kt1 = (c + 1) << 5;
#pragma unroll
            for (int s = 0; s < 4; s++)
#pragma unroll
                for (int j = 0; j < 2; j++)
                    st[s][j] = *(const uint4*)(srcs[s] + (size_t)(rb[s] + lr + j * 64) * Ktot + kt1 + lq * 8);
        }

#pragma unroll
        for (int kb = 0; kb < 2; kb++) {
            uint32_t Ah[4][4], Al[4][4], Bh[2][4], Bl[2][4];
#pragma unroll
            for (int mt = 0; mt < 4; mt++) {
                ldsm4(Ah[mt], mats[0] + a_off + (uint32_t)(mt * 1280 + kb * 32));
                ldsm4(Al[mt], mats[1] + a_off + (uint32_t)(mt * 1280 + kb * 32));
            }
#pragma unroll
            for (int t2 = 0; t2 < 2; t2++) {
                ldsm4(Bh[t2], mats[2] + b_off + (uint32_t)(t2 * 1280 + kb * 32));
                ldsm4(Bl[t2], mats[3] + b_off + (uint32_t)(t2 * 1280 + kb * 32));
            }
#pragma unroll
            for (int mt = 0; mt < 4; mt++)
#pragma unroll
                for (int nt = 0; nt < 4; nt++) {
                    const uint32_t* bh = &Bh[nt >> 1][(nt & 1) * 2];
                    const uint32_t* bl = &Bl[nt >> 1][(nt & 1) * 2];
                    mma_bf16(acc[mt][nt], Ah[mt], bh);
                    mma_bf16(acc[mt][nt], Ah[mt], bl);
                    mma_bf16(acc[mt][nt], Al[mt], bh);
                    mma_bf16(acc[mt][nt], Al[mt], bl);
                }
        }
    }

    // epilogue
    float* Cb = C + (size_t)blockIdx.z * M * N;
#pragma unroll
    for (int mt = 0; mt < 4; mt++)
#pragma unroll
        for (int nt = 0; nt < 4; nt++) {
            const int row = m0 + wm * 64 + mt * 16 + (lane >> 2);
            const int col = n0 + wn * 32 + nt * 8 + (lane & 3) * 2;
            float2 v0 = { acc[mt][nt][0], acc[mt][nt][1] };
            float2 v1 = { acc[mt][nt][2], acc[mt][nt][3] };
            *(float2*)&Cb[(size_t)row * N + col]       = v0;
            *(float2*)&Cb[(size_t)(row + 8) * N + col] = v1;
        }
#endif
}

// ---------------------------------------------------------------------------
// Conversions
// ---------------------------------------------------------------------------
__global__ void __launch_bounds__(256)
convert_split_kernel(const float* __restrict__ in,
                     __nv_bfloat16* __restrict__ hi,
                     __nv_bfloat16* __restrict__ lo, size_t n4) {
    size_t i = (size_t)blockIdx.x * 256 + threadIdx.x;
    if (i >= n4) return;
    float4 v = *(const float4*)(in + i * 4);
    __nv_bfloat16 h0, h1, h2, h3, l0, l1, l2, l3;
    split_bf16(v.x, h0, l0); split_bf16(v.y, h1, l1);
    split_bf16(v.z, h2, l2); split_bf16(v.w, h3, l3);
    __nv_bfloat162* ph = (__nv_bfloat162*)(hi + i * 4);
    __nv_bfloat162* pl = (__nv_bfloat162*)(lo + i * 4);
    ph[0] = __nv_bfloat162(h0, h1); ph[1] = __nv_bfloat162(h2, h3);
    pl[0] = __nv_bfloat162(l0, l1); pl[1] = __nv_bfloat162(l2, l3);
}

__global__ void __launch_bounds__(256)
transpose_split_kernel(const float* __restrict__ Kin,
                       __nv_bfloat16* __restrict__ KThi,
                       __nv_bfloat16* __restrict__ KTlo) {
    __shared__ float tile[32][33];
    int b = blockIdx.z;
    int t0 = blockIdx.x * 32, d0 = blockIdx.y * 32;
    int tx = threadIdx.x & 31, ty = threadIdx.x >> 5;
    const float* src = Kin + (size_t)b * TK * HD;
#pragma unroll
    for (int r = 0; r < 4; r++)
        tile[ty + 8 * r][tx] = src[(size_t)(t0 + ty + 8 * r) * HD + d0 + tx];
    __syncthreads();
    __nv_bfloat16* oh = KThi + (size_t)b * HD * TK;
    __nv_bfloat16* ol = KTlo + (size_t)b * HD * TK;
#pragma unroll
    for (int r = 0; r < 4; r++) {
        int d = d0 + ty + 8 * r, t = t0 + tx;
        float v = tile[tx][ty + 8 * r];
        __nv_bfloat16 h, l; split_bf16(v, h, l);
        oh[(size_t)d * TK + t] = h;
        ol[(size_t)d * TK + t] = l;
    }
}

// ---------------------------------------------------------------------------
// Row softmax over TK, fp32 in, bf16 hi/lo out
// ---------------------------------------------------------------------------
__global__ void __launch_bounds__(256)
softmax_kernel(const float* __restrict__ E,
               __nv_bfloat16* __restrict__ Phi, __nv_bfloat16* __restrict__ Plo)
{
    const size_t row = blockIdx.x;
    const float* e = E + row * (size_t)TK;
    const int tid = threadIdx.x;
    const int lane = tid & 31, warp = tid >> 5;
    __shared__ float red[32];

    float v[8];
    float m = -INFINITY;
#pragma unroll
    for (int i = 0; i < 8; i++) { v[i] = e[tid + i * 256]; m = fmaxf(m, v[i]); }
#pragma unroll
    for (int o = 16; o > 0; o >>= 1) m = fmaxf(m, __shfl_xor_sync(0xffffffffu, m, o));
    if (lane == 0) red[warp] = m;
    __syncthreads();
    if (warp == 0) {
        float t = red[lane & 7];
#pragma unroll
        for (int o = 4; o > 0; o >>= 1) t = fmaxf(t, __shfl_xor_sync(0xffffffffu, t, o));
        red[lane] = t;
    }
    __syncthreads();
    m = red[0];

    float s = 0.0f;
#pragma unroll
    for (int i = 0; i < 8; i++) { v[i] = __expf(v[i] - m); s += v[i]; }
#pragma unroll
    for (int o = 16; o > 0; o >>= 1) s += __shfl_xor_sync(0xffffffffu, s, o);
    __syncthreads();
    if (lane == 0) red[warp] = s;
    __syncthreads();
    if (warp == 0) {
        float t = red[lane & 7];
#pragma unroll
        for (int o = 4; o > 0; o >>= 1) t += __shfl_xor_sync(0xffffffffu, t, o);
        red[lane] = t;
    }
    __syncthreads();
    const float inv = 1.0f / red[0];

#pragma unroll
    for (int i = 0; i < 8; i++) {
        const float p = v[i] * inv;
        __nv_bfloat16 h, l; split_bf16(p, h, l);
        const size_t idx = row * (size_t)TK + tid + i * 256;
        Phi[idx] = h; Plo[idx] = l;
    }
}

// ---------------------------------------------------------------------------
extern "C" void kernel_launch(void* const* d_in, const int* in_sizes, int n_in,
                              void* d_out, int out_size)
{
    const float* Q  = (const float*)d_in[0];
    const float* Kt = (const float*)d_in[1];
    float* O = (float*)d_out;

    float *E; __nv_bfloat16 *Qhi, *Qlo, *Khi, *Klo, *KThi, *KTlo, *Phi, *Plo;
    cudaGetSymbolAddress((void**)&E,    g_E);
    cudaGetSymbolAddress((void**)&Qhi,  g_Qhi);
    cudaGetSymbolAddress((void**)&Qlo,  g_Qlo);
    cudaGetSymbolAddress((void**)&Khi,  g_Khi);
    cudaGetSymbolAddress((void**)&Klo,  g_Klo);
    cudaGetSymbolAddress((void**)&KThi, g_KThi);
    cudaGetSymbolAddress((void**)&KTlo, g_KTlo);
    cudaGetSymbolAddress((void**)&Phi,  g_Phi);
    cudaGetSymbolAddress((void**)&Plo,  g_Plo);

    cudaFuncSetAttribute(gemm_split_kernel,
                         cudaFuncAttributeMaxDynamicSharedMemorySize, GEMM_SMEM);

    {
        size_t n4 = (size_t)BATCH * TQ * HD / 4;
        convert_split_kernel<<<(unsigned)((n4 + 255) / 256), 256>>>(Q, Qhi, Qlo, n4);
        convert_split_kernel<<<(unsigned)((n4 + 255) / 256), 256>>>(Kt, Khi, Klo, n4);
    }
    {
        dim3 grid(TK / 32, HD / 32, BATCH);
        transpose_split_kernel<<<grid, 256>>>(Kt, KThi, KTlo);
    }
    // GEMM1: E = Q K^T  (M=TQ, N=TK, Ktot=HD)
    {
        dim3 grid(TK / 128, TQ / 128, BATCH);
        gemm_split_kernel<<<grid, 256, GEMM_SMEM>>>(Qhi, Qlo, Khi, Klo, E, TQ, TK, HD);
    }
    softmax_kernel<<<BATCH * TQ, 256>>>(E, Phi, Plo);
    // GEMM2: O = P KT^T  (M=TQ, N=HD, Ktot=TK)
    {
        dim3 grid(HD / 128, TQ / 128, BATCH);
        gemm_split_kernel<<<grid, 256, GEMM_SMEM>>>(Phi, Plo, KThi, KTlo, O, TQ, HD, TK);
    }
    (void)in_sizes; (void)n_in; (void)out_size;
}

// round 6
// speedup vs baseline: 5.3443x; 1.3378x over previous
#include <cuda_runtime.h>
#include <cuda_bf16.h>
#include <cstdint>
#include <math.h>

#define BATCH 8
#define TQ    2048
#define TK    2048
#define HD    1024

#if defined(__CUDA_ARCH_FEAT_SM103_ALL) || defined(__CUDA_ARCH_FEAT_SM100_ALL)
#define HAS_TCGEN05 1
#else
#define HAS_TCGEN05 0
#endif

// ---------------------------------------------------------------------------
// Device scratch
// ---------------------------------------------------------------------------
__device__ float         g_E   [(size_t)BATCH * TQ * TK];
__device__ __nv_bfloat16 g_Qhi [(size_t)BATCH * TQ * HD];
__device__ __nv_bfloat16 g_Qlo [(size_t)BATCH * TQ * HD];
__device__ __nv_bfloat16 g_Khi [(size_t)BATCH * TK * HD];
__device__ __nv_bfloat16 g_Klo [(size_t)BATCH * TK * HD];
__device__ __nv_bfloat16 g_KThi[(size_t)BATCH * HD * TK];
__device__ __nv_bfloat16 g_KTlo[(size_t)BATCH * HD * TK];
__device__ __nv_bfloat16 g_Phi [(size_t)BATCH * TQ * TK];
__device__ __nv_bfloat16 g_Plo [(size_t)BATCH * TQ * TK];

// ---------------------------------------------------------------------------
// Common helpers
// ---------------------------------------------------------------------------
__device__ __forceinline__ uint32_t smem_u32(const void* p) {
    uint32_t a;
    asm("{ .reg .u64 t; cvta.to.shared.u64 t, %1; cvt.u32.u64 %0, t; }" : "=r"(a) : "l"(p));
    return a;
}

__device__ __forceinline__ void sts128(uint32_t addr, uint4 v) {
    asm volatile("st.shared.v4.b32 [%0], {%1,%2,%3,%4};"
                 :: "r"(addr), "r"(v.x), "r"(v.y), "r"(v.z), "r"(v.w) : "memory");
}

__device__ __forceinline__ void split_bf16(float x, __nv_bfloat16& h, __nv_bfloat16& l) {
    h = __float2bfloat16(x);
    l = __float2bfloat16(x - __bfloat162float(h));
}

#define CP_ASYNC16(dst, src) \
    asm volatile("cp.async.cg.shared.global [%0], [%1], 16;" :: "r"(dst), "l"(src) : "memory")
#define CP_COMMIT()  asm volatile("cp.async.commit_group;" ::: "memory")
#define CP_WAIT0()   asm volatile("cp.async.wait_group 0;" ::: "memory")

// ---------------------------------------------------------------------------
// tcgen05 helpers (only in the sm_103a feature pass)
// ---------------------------------------------------------------------------
#if HAS_TCGEN05
__device__ __forceinline__ uint32_t elect_one() {
    uint32_t p;
    asm volatile("{\n\t.reg .pred p;\n\telect.sync _|p, 0xFFFFFFFF;\n\tselp.b32 %0, 1, 0, p;\n\t}"
                 : "=r"(p));
    return p;
}

#define MBARRIER_INIT(addr, cnt) \
    asm volatile("mbarrier.init.shared.b64 [%0], %1;" :: "r"((uint32_t)(addr)), "r"((uint32_t)(cnt)) : "memory")

#define MBARRIER_WAIT_PARITY(addr, parity) do {                                              \
    uint32_t _m = (uint32_t)(addr); uint32_t _p = (uint32_t)(parity); uint32_t _d;            \
    asm volatile("{\n\t.reg .pred p;\n\t"                                                     \
        "mbarrier.try_wait.parity.acquire.cta.shared::cta.b64 p, [%1], %2;\n\t"               \
        "selp.b32 %0, 1, 0, p;\n\t}" : "=r"(_d) : "r"(_m), "r"(_p) : "memory");               \
    if (!_d) {                                                                                \
        asm volatile("{\n\t.reg .pred P1;\n\t"                                                \
            "WL_%=:\n\t"                                                                      \
            "mbarrier.try_wait.parity.acquire.cta.shared::cta.b64 P1, [%0], %1, 0x989680;\n\t"\
            "@P1 bra.uni WD_%=;\n\t"                                                          \
            "bra.uni WL_%=;\n\t"                                                              \
            "WD_%=:\n\t}" :: "r"(_m), "r"(_p) : "memory");                                    \
    }                                                                                         \
} while (0)

#define TCGEN05_ALLOC(smem_addr, ncols) \
    asm volatile("tcgen05.alloc.cta_group::1.sync.aligned.shared::cta.b32 [%0], %1;" \
                 :: "r"((uint32_t)(smem_addr)), "r"((uint32_t)(ncols)) : "memory")
#define TCGEN05_DEALLOC(tmem, ncols) \
    asm volatile("tcgen05.dealloc.cta_group::1.sync.aligned.b32 %0, %1;" :: "r"(tmem), "r"((uint32_t)(ncols)))
#define TCGEN05_COMMIT(mbar) \
    asm volatile("tcgen05.commit.cta_group::1.mbarrier::arrive::one.shared::cluster.b64 [%0];" \
                 :: "r"((uint32_t)(mbar)) : "memory")
#define TCGEN05_FENCE_AFTER()  asm volatile("tcgen05.fence::after_thread_sync;"  ::: "memory")
#define TCGEN05_FENCE_BEFORE() asm volatile("tcgen05.fence::before_thread_sync;" ::: "memory")
#define TCGEN05_WAIT_LD()      asm volatile("tcgen05.wait::ld.sync.aligned;"     ::: "memory")
#define FENCE_PROXY_ASYNC()    asm volatile("fence.proxy.async.shared::cta;"     ::: "memory")

#define TCGEN05_LD_32X32B_X32(r, tmem_addr) \
    asm volatile( \
        "tcgen05.ld.sync.aligned.32x32b.x32.b32 " \
        "{%0, %1, %2, %3, %4, %5, %6, %7, " \
        " %8, %9, %10, %11, %12, %13, %14, %15, " \
        " %16, %17, %18, %19, %20, %21, %22, %23, " \
        " %24, %25, %26, %27, %28, %29, %30, %31}, [%32];" \
        : "=r"((r)[0]),  "=r"((r)[1]),  "=r"((r)[2]),  "=r"((r)[3]), \
          "=r"((r)[4]),  "=r"((r)[5]),  "=r"((r)[6]),  "=r"((r)[7]), \
          "=r"((r)[8]),  "=r"((r)[9]),  "=r"((r)[10]), "=r"((r)[11]), \
          "=r"((r)[12]), "=r"((r)[13]), "=r"((r)[14]), "=r"((r)[15]), \
          "=r"((r)[16]), "=r"((r)[17]), "=r"((r)[18]), "=r"((r)[19]), \
          "=r"((r)[20]), "=r"((r)[21]), "=r"((r)[22]), "=r"((r)[23]), \
          "=r"((r)[24]), "=r"((r)[25]), "=r"((r)[26]), "=r"((r)[27]), \
          "=r"((r)[28]), "=r"((r)[29]), "=r"((r)[30]), "=r"((r)[31]) \
        : "r"(tmem_addr))

__device__ __forceinline__ void mma_f16_ss(uint32_t d, uint64_t ad, uint64_t bd,
                                           uint32_t idesc, bool acc) {
    uint32_t en = acc ? 1u : 0u;
    asm volatile(
        "{\n\t.reg .pred p;\n\tsetp.ne.u32 p, %5, 0;\n\t"
        "tcgen05.mma.cta_group::1.kind::f16 [%0], %1, %2, %3, {%4, %4, %4, %4}, p;\n\t}"
        :: "r"(d), "l"(ad), "l"(bd), "r"(idesc), "r"(0u), "r"(en) : "memory");
}

__device__ __forceinline__ uint64_t make_desc(uint32_t addr) {
    const uint64_t base = (2ULL << 61) | (1ULL << 46) | (64ULL << 32) | (1ULL << 16);
    return base | ((uint64_t)(addr >> 4) & 0x3FFF);
}
// dtype=F32, a/b=BF16, N=256 (32<<17), M=128 (8<<24)
#define MMA_IDESC_N256 0x8400490u
#endif  // HAS_TCGEN05

// ---------------------------------------------------------------------------
// HMMA fallback helpers
// ---------------------------------------------------------------------------
__device__ __forceinline__ void ldsm4(uint32_t* r, uint32_t addr) {
    asm volatile("ldmatrix.sync.aligned.m8n8.x4.shared.b16 {%0,%1,%2,%3}, [%4];"
                 : "=r"(r[0]), "=r"(r[1]), "=r"(r[2]), "=r"(r[3]) : "r"(addr));
}

__device__ __forceinline__ void mma_bf16(float* d, const uint32_t* a, const uint32_t* b) {
    asm volatile(
        "mma.sync.aligned.m16n8k16.row.col.f32.bf16.bf16.f32 "
        "{%0,%1,%2,%3}, {%4,%5,%6,%7}, {%8,%9}, {%0,%1,%2,%3};"
        : "+f"(d[0]), "+f"(d[1]), "+f"(d[2]), "+f"(d[3])
        : "r"(a[0]), "r"(a[1]), "r"(a[2]), "r"(a[3]), "r"(b[0]), "r"(b[1]));
}

// ---------------------------------------------------------------------------
// GEMM: C[M,N] = (Ahi+Alo)[M,Kt] * (Bhi+Blo)[N,Kt]^T, fp32 out.
// CTA tile 128(M) x 256(N); K-chunk 64; 2-stage cp.async pipeline.
// Grid: x = N/256, y = M/128, z = batch.
// ---------------------------------------------------------------------------
#define SM_TMEMPTR  0
#define SM_MBAR0    8
#define SM_MBAR1    16
#define SM_BUF      1024
#define STAGE_BYTES 98304          // Ahi 16K | Alo 16K | Bhi 32K | Blo 32K
#define GEMM_SMEM   (SM_BUF + 2 * STAGE_BYTES)

__global__ void __launch_bounds__(256, 1)
gemm_split_kernel(const __nv_bfloat16* __restrict__ Ahi, const __nv_bfloat16* __restrict__ Alo,
                  const __nv_bfloat16* __restrict__ Bhi, const __nv_bfloat16* __restrict__ Blo,
                  float* __restrict__ C, int M, int N, int Ktot)
{
#if HAS_TCGEN05
    extern __shared__ char smem[];
    const uint32_t sb = smem_u32(smem);
    const int tid = threadIdx.x;
    const int wid = tid >> 5, lid = tid & 31;
    const int m0 = blockIdx.y * 128, n0 = blockIdx.x * 256;

    const size_t offA = (size_t)blockIdx.z * M * Ktot;
    const size_t offB = (size_t)blockIdx.z * N * Ktot;
    const __nv_bfloat16* pA[2] = { Ahi + offA, Alo + offA };
    const __nv_bfloat16* pB[2] = { Bhi + offB, Blo + offB };

    if (wid == 0) TCGEN05_ALLOC(sb + SM_TMEMPTR, 256);
    if (tid == 0) { MBARRIER_INIT(sb + SM_MBAR0, 1); MBARRIER_INIT(sb + SM_MBAR1, 1); }
    __syncthreads();
    uint32_t tmem;
    asm volatile("ld.shared.b32 %0, [%1];" : "=r"(tmem) : "r"(sb + SM_TMEMPTR));

    const int nchunks = Ktot >> 6;
    int ph0 = 0, ph1 = 0;

    for (int c = 0; c < nchunks; c++) {
        const int buf = c & 1;
        const uint32_t stage = sb + SM_BUF + buf * STAGE_BYTES;
        if (c >= 2) {
            if (buf == 0) { MBARRIER_WAIT_PARITY(sb + SM_MBAR0, ph0); ph0 ^= 1; }
            else          { MBARRIER_WAIT_PARITY(sb + SM_MBAR1, ph1); ph1 ^= 1; }
        }
        const int kt0 = c << 6;

        // ---- cp.async loads: A hi/lo (128 rows x 128B), B hi/lo (256 rows x 128B)
#pragma unroll
        for (int s = 0; s < 2; s++) {
            const uint32_t dst = stage + s * 16384;
#pragma unroll
            for (int j = 0; j < 4; j++) {
                const int idx = tid + j * 256;            // 0..1023
                const int row = idx >> 3, c16 = idx & 7;
                const __nv_bfloat16* src = pA[s] + (size_t)(m0 + row) * Ktot + kt0 + c16 * 8;
                uint32_t off = (uint32_t)(row * 128 + c16 * 16);
                CP_ASYNC16(dst + (off ^ ((off >> 3) & 0x70)), src);
            }
        }
#pragma unroll
        for (int s = 0; s < 2; s++) {
            const uint32_t dst = stage + 32768 + s * 32768;
#pragma unroll
            for (int j = 0; j < 8; j++) {
                const int idx = tid + j * 256;            // 0..2047
                const int row = idx >> 3, c16 = idx & 7;
                const __nv_bfloat16* src = pB[s] + (size_t)(n0 + row) * Ktot + kt0 + c16 * 8;
                uint32_t off = (uint32_t)(row * 128 + c16 * 16);
                CP_ASYNC16(dst + (off ^ ((off >> 3) & 0x70)), src);
            }
        }
        CP_COMMIT();
        CP_WAIT0();
        __syncthreads();
        FENCE_PROXY_ASYNC();

        if (wid == 0 && elect_one()) {
            const uint64_t dAh = make_desc(stage + 0);
            const uint64_t dAl = make_desc(stage + 16384);
            const uint64_t dBh = make_desc(stage + 32768);
            const uint64_t dBl = make_desc(stage + 65536);
            const bool first = (c == 0);
#pragma unroll
            for (int s = 0; s < 4; s++)
                mma_f16_ss(tmem, dAh + s * 2, dBh + s * 2, MMA_IDESC_N256, !(first && s == 0));
#pragma unroll
            for (int s = 0; s < 4; s++)
                mma_f16_ss(tmem, dAh + s * 2, dBl + s * 2, MMA_IDESC_N256, true);
#pragma unroll
            for (int s = 0; s < 4; s++)
                mma_f16_ss(tmem, dAl + s * 2, dBh + s * 2, MMA_IDESC_N256, true);
#pragma unroll
            for (int s = 0; s < 4; s++)
                mma_f16_ss(tmem, dAl + s * 2, dBl + s * 2, MMA_IDESC_N256, true);
            TCGEN05_COMMIT(sb + (buf ? SM_MBAR1 : SM_MBAR0));
        }
    }

    MBARRIER_WAIT_PARITY(sb + SM_MBAR0, ph0);
    MBARRIER_WAIT_PARITY(sb + SM_MBAR1, ph1);
    TCGEN05_FENCE_AFTER();

    // epilogue: warp w -> rows (w&3)*32+lid, col half (w>>2)*128
    {
        const int sub = wid & 3, half = wid >> 2;
        const int row = sub * 32 + lid;
        float* crow = C + (size_t)blockIdx.z * M * N + (size_t)(m0 + row) * N + n0 + half * 128;
#pragma unroll
        for (int g = 0; g < 4; g++) {
            uint32_t regs[32];
            TCGEN05_LD_32X32B_X32(regs, tmem + half * 128 + g * 32);
            TCGEN05_WAIT_LD();
#pragma unroll
            for (int q = 0; q < 8; q++) {
                float4 f;
                f.x = __uint_as_float(regs[q * 4 + 0]);
                f.y = __uint_as_float(regs[q * 4 + 1]);
                f.z = __uint_as_float(regs[q * 4 + 2]);
                f.w = __uint_as_float(regs[q * 4 + 3]);
                *(float4*)(crow + g * 32 + q * 4) = f;
            }
        }
    }
    TCGEN05_FENCE_BEFORE();
    __syncthreads();
    if (wid == 0) TCGEN05_DEALLOC(tmem, 256);

#else
    // ===================== HMMA (mma.sync) fallback =====================
    // Processes the 128x256 tile as two sequential 128x128 halves (R4 scheme).
    extern __shared__ char smem[];
    const uint32_t sb = smem_u32(smem);
    const int tid  = threadIdx.x;
    const int lane = tid & 31, wid = tid >> 5;
    const int wm = wid & 1, wn = wid >> 1;
    const int m0 = blockIdx.y * 128;

    const size_t offA = (size_t)blockIdx.z * M * Ktot;
    const size_t offB = (size_t)blockIdx.z * N * Ktot;
    const uint32_t mats[4] = { sb, sb + 10240u, sb + 20480u, sb + 30720u };

    const uint32_t a_off = (uint32_t)((wm * 64 + (lane & 15)) * 80 + (lane >> 4) * 16);
    const uint32_t b_off = (uint32_t)((wn * 32 + ((lane >> 4) & 1) * 8 + (lane & 7)) * 80
                                      + ((lane >> 3) & 1) * 16);
    const int lr = tid >> 2, lq = tid & 3;
    const int nchunks = Ktot >> 5;

    for (int h = 0; h < 2; h++) {
        const int n0 = blockIdx.x * 256 + h * 128;
        const __nv_bfloat16* srcs[4] = { Ahi + offA, Alo + offA, Bhi + offB, Blo + offB };
        const int rb[4] = { m0, m0, n0, n0 };

        float acc[4][4][4];
#pragma unroll
        for (int i = 0; i < 4; i++)
#pragma unroll
            for (int j = 0; j < 4; j++)
#pragma unroll
                for (int q = 0; q < 4; q++) acc[i][j][q] = 0.0f;

        uint4 st[4][2];
#pragma unroll 1
        for (int c = 0; c < nchunks; c++) {
            if (c == 0) {
#pragma unroll
                for (int s = 0; s < 4; s++)
#pragma unroll
                    for (int j = 0; j < 2; j++)
                        st[s][j] = *(const uint4*)(srcs[s] + (size_t)(rb[s] + lr + j * 64) * Ktot + lq * 8);
            }
            __syncthreads();
#pragma unroll
            for (int s = 0; s < 4; s++)
#pragma unroll
                for (int j = 0; j < 2; j++)
                    sts128(mats[s] + (uint32_t)((lr + j * 64) * 80 + lq * 16), st[s][j]);
            __syncthreads();

            if (c + 1 < nchunks) {
                const int kt1 = (c + 1) << 5;
#pragma unroll
                for (int s = 0; s < 4; s++)
#pragma unroll
                    for (int j = 0; j < 2; j++)
                        st[s][j] = *(const uint4*)(srcs[s] + (size_t)(rb[s] + lr + j * 64) * Ktot + kt1 + lq * 8);
            }

#pragma unroll
            for (int kb = 0; kb < 2; kb++) {
                uint32_t Ah[4][4], Al[4][4], Bh[2][4], Bl[2][4];
#pragma unroll
                for (int mt = 0; mt < 4; mt++) {
                    ldsm4(Ah[mt], mats[0] + a_off + (uint32_t)(mt * 1280 + kb * 32));
                    ldsm4(Al[mt], mats[1] + a_off + (uint32_t)(mt * 1280 + kb * 32));
                }
#pragma unroll
                for (int t2 = 0; t2 < 2; t2++) {
                    ldsm4(Bh[t2], mats[2] + b_off + (uint32_t)(t2 * 1280 + kb * 32));
                    ldsm4(Bl[t2], mats[3] + b_off + (uint32_t)(t2 * 1280 + kb * 32));
                }
#pragma unroll
                for (int mt = 0; mt < 4; mt++)
#pragma unroll
                    for (int nt = 0; nt < 4; nt++) {
                        const uint32_t* bh = &Bh[nt >> 1][(nt & 1) * 2];
                        const uint32_t* bl = &Bl[nt >> 1][(nt & 1) * 2];
                        mma_bf16(acc[mt][nt], Ah[mt], bh);
                        mma_bf16(acc[mt][nt], Ah[mt], bl);
                        mma_bf16(acc[mt][nt], Al[mt], bh);
                        mma_bf16(acc[mt][nt], Al[mt], bl);
                    }
            }
        }

        float* Cb = C + (size_t)blockIdx.z * M * N;
#pragma unroll
        for (int mt = 0; mt < 4; mt++)
#pragma unroll
            for (int nt = 0; nt < 4; nt++) {
                const int row = m0 + wm * 64 + mt * 16 + (lane >> 2);
                const int col = n0 + wn * 32 + nt * 8 + (lane & 3) * 2;
                float2 v0 = { acc[mt][nt][0], acc[mt][nt][1] };
                float2 v1 = { acc[mt][nt][2], acc[mt][nt][3] };
                *(float2*)&Cb[(size_t)row * N + col]       = v0;
                *(float2*)&Cb[(size_t)(row + 8) * N + col] = v1;
            }
        __syncthreads();
    }
#endif
}

// ---------------------------------------------------------------------------
// Conversions
// ---------------------------------------------------------------------------
__global__ void __launch_bounds__(256)
convert_split_kernel(const float* __restrict__ in,
                     __nv_bfloat16* __restrict__ hi,
                     __nv_bfloat16* __restrict__ lo, size_t n4) {
    size_t i = (size_t)blockIdx.x * 256 + threadIdx.x;
    if (i >= n4) return;
    float4 v = *(const float4*)(in + i * 4);
    __nv_bfloat16 h0, h1, h2, h3, l0, l1, l2, l3;
    split_bf16(v.x, h0, l0); split_bf16(v.y, h1, l1);
    split_bf16(v.z, h2, l2); split_bf16(v.w, h3, l3);
    __nv_bfloat162* ph = (__nv_bfloat162*)(hi + i * 4);
    __nv_bfloat162* pl = (__nv_bfloat162*)(lo + i * 4);
    ph[0] = __nv_bfloat162(h0, h1); ph[1] = __nv_bfloat162(h2, h3);
    pl[0] = __nv_bfloat162(l0, l1); pl[1] = __nv_bfloat162(l2, l3);
}

__global__ void __launch_bounds__(256)
transpose_split_kernel(const float* __restrict__ Kin,
                       __nv_bfloat16* __restrict__ KThi,
                       __nv_bfloat16* __restrict__ KTlo) {
    __shared__ float tile[32][33];
    int b = blockIdx.z;
    int t0 = blockIdx.x * 32, d0 = blockIdx.y * 32;
    int tx = threadIdx.x & 31, ty = threadIdx.x >> 5;
    const float* src = Kin + (size_t)b * TK * HD;
#pragma unroll
    for (int r = 0; r < 4; r++)
        tile[ty + 8 * r][tx] = src[(size_t)(t0 + ty + 8 * r) * HD + d0 + tx];
    __syncthreads();
    __nv_bfloat16* oh = KThi + (size_t)b * HD * TK;
    __nv_bfloat16* ol = KTlo + (size_t)b * HD * TK;
#pragma unroll
    for (int r = 0; r < 4; r++) {
        int d = d0 + ty + 8 * r, t = t0 + tx;
        float v = tile[tx][ty + 8 * r];
        __nv_bfloat16 h, l; split_bf16(v, h, l);
        oh[(size_t)d * TK + t] = h;
        ol[(size_t)d * TK + t] = l;
    }
}

// ---------------------------------------------------------------------------
// Row softmax over TK, fp32 in, bf16 hi/lo out
// ---------------------------------------------------------------------------
__global__ void __launch_bounds__(256)
softmax_kernel(const float* __restrict__ E,
               __nv_bfloat16* __restrict__ Phi, __nv_bfloat16* __restrict__ Plo)
{
    const size_t row = blockIdx.x;
    const float* e = E + row * (size_t)TK;
    const int tid = threadIdx.x;
    const int lane = tid & 31, warp = tid >> 5;
    __shared__ float red[32];

    float v[8];
    float m = -INFINITY;
#pragma unroll
    for (int i = 0; i < 8; i++) { v[i] = e[tid + i * 256]; m = fmaxf(m, v[i]); }
#pragma unroll
    for (int o = 16; o > 0; o >>= 1) m = fmaxf(m, __shfl_xor_sync(0xffffffffu, m, o));
    if (lane == 0) red[warp] = m;
    __syncthreads();
    if (warp == 0) {
        float t = red[lane & 7];
#pragma unroll
        for (int o = 4; o > 0; o >>= 1) t = fmaxf(t, __shfl_xor_sync(0xffffffffu, t, o));
        red[lane] = t;
    }
    __syncthreads();
    m = red[0];

    float s = 0.0f;
#pragma unroll
    for (int i = 0; i < 8; i++) { v[i] = __expf(v[i] - m); s += v[i]; }
#pragma unroll
    for (int o = 16; o > 0; o >>= 1) s += __shfl_xor_sync(0xffffffffu, s, o);
    __syncthreads();
    if (lane == 0) red[warp] = s;
    __syncthreads();
    if (warp == 0) {
        float t = red[lane & 7];
#pragma unroll
        for (int o = 4; o > 0; o >>= 1) t += __shfl_xor_sync(0xffffffffu, t, o);
        red[lane] = t;
    }
    __syncthreads();
    const float inv = 1.0f / red[0];

#pragma unroll
    for (int i = 0; i < 8; i++) {
        const float p = v[i] * inv;
        __nv_bfloat16 h, l; split_bf16(p, h, l);
        const size_t idx = row * (size_t)TK + tid + i * 256;
        Phi[idx] = h; Plo[idx] = l;
    }
}

// ---------------------------------------------------------------------------
extern "C" void kernel_launch(void* const* d_in, const int* in_sizes, int n_in,
                              void* d_out, int out_size)
{
    const float* Q  = (const float*)d_in[0];
    const float* Kt = (const float*)d_in[1];
    float* O = (float*)d_out;

    float *E; __nv_bfloat16 *Qhi, *Qlo, *Khi, *Klo, *KThi, *KTlo, *Phi, *Plo;
    cudaGetSymbolAddress((void**)&E,    g_E);
    cudaGetSymbolAddress((void**)&Qhi,  g_Qhi);
    cudaGetSymbolAddress((void**)&Qlo,  g_Qlo);
    cudaGetSymbolAddress((void**)&Khi,  g_Khi);
    cudaGetSymbolAddress((void**)&Klo,  g_Klo);
    cudaGetSymbolAddress((void**)&KThi, g_KThi);
    cudaGetSymbolAddress((void**)&KTlo, g_KTlo);
    cudaGetSymbolAddress((void**)&Phi,  g_Phi);
    cudaGetSymbolAddress((void**)&Plo,  g_Plo);

    cudaFuncSetAttribute(gemm_split_kernel,
                         cudaFuncAttributeMaxDynamicSharedMemorySize, GEMM_SMEM);

    {
        size_t n4 = (size_t)BATCH * TQ * HD / 4;
        convert_split_kernel<<<(unsigned)((n4 + 255) / 256), 256>>>(Q, Qhi, Qlo, n4);
        convert_split_kernel<<<(unsigned)((n4 + 255) / 256), 256>>>(Kt, Khi, Klo, n4);
    }
    {
        dim3 grid(TK / 32, HD / 32, BATCH);
        transpose_split_kernel<<<grid, 256>>>(Kt, KThi, KTlo);
    }
    // GEMM1: E = Q K^T  (M=TQ, N=TK, Ktot=HD)
    {
        dim3 grid(TK / 256, TQ / 128, BATCH);
        gemm_split_kernel<<<grid, 256, GEMM_SMEM>>>(Qhi, Qlo, Khi, Klo, E, TQ, TK, HD);
    }
    softmax_kernel<<<BATCH * TQ, 256>>>(E, Phi, Plo);
    // GEMM2: O = P KT^T  (M=TQ, N=HD, Ktot=TK)
    {
        dim3 grid(HD / 256, TQ / 128, BATCH);
        gemm_split_kernel<<<grid, 256, GEMM_SMEM>>>(Phi, Plo, KThi, KTlo, O, TQ, HD, TK);
    }
    (void)in_sizes; (void)n_in; (void)out_size;
}

// round 7
// speedup vs baseline: 5.7684x; 1.0794x over previous
#include <cuda_runtime.h>
#include <cuda_bf16.h>
#include <cstdint>
#include <math.h>

#define BATCH 8
#define TQ    2048
#define TK    2048
#define HD    1024

#if defined(__CUDA_ARCH_FEAT_SM103_ALL) || defined(__CUDA_ARCH_FEAT_SM100_ALL)
#define HAS_TCGEN05 1
#else
#define HAS_TCGEN05 0
#endif

// ---------------------------------------------------------------------------
// Device scratch
// ---------------------------------------------------------------------------
__device__ float         g_E   [(size_t)BATCH * TQ * TK];
__device__ __nv_bfloat16 g_Qhi [(size_t)BATCH * TQ * HD];
__device__ __nv_bfloat16 g_Qlo [(size_t)BATCH * TQ * HD];
__device__ __nv_bfloat16 g_Khi [(size_t)BATCH * TK * HD];
__device__ __nv_bfloat16 g_Klo [(size_t)BATCH * TK * HD];
__device__ __nv_bfloat16 g_KThi[(size_t)BATCH * HD * TK];
__device__ __nv_bfloat16 g_KTlo[(size_t)BATCH * HD * TK];
__device__ __nv_bfloat16 g_Phi [(size_t)BATCH * TQ * TK];
__device__ __nv_bfloat16 g_Plo [(size_t)BATCH * TQ * TK];

// ---------------------------------------------------------------------------
// Common helpers
// ---------------------------------------------------------------------------
__device__ __forceinline__ uint32_t smem_u32(const void* p) {
    uint32_t a;
    asm("{ .reg .u64 t; cvta.to.shared.u64 t, %1; cvt.u32.u64 %0, t; }" : "=r"(a) : "l"(p));
    return a;
}

__device__ __forceinline__ void sts128(uint32_t addr, uint4 v) {
    asm volatile("st.shared.v4.b32 [%0], {%1,%2,%3,%4};"
                 :: "r"(addr), "r"(v.x), "r"(v.y), "r"(v.z), "r"(v.w) : "memory");
}

__device__ __forceinline__ void split_bf16(float x, __nv_bfloat16& h, __nv_bfloat16& l) {
    h = __float2bfloat16(x);
    l = __float2bfloat16(x - __bfloat162float(h));
}

#define CP_ASYNC16(dst, src) \
    asm volatile("cp.async.cg.shared.global [%0], [%1], 16;" :: "r"(dst), "l"(src) : "memory")
#define CP_COMMIT()  asm volatile("cp.async.commit_group;" ::: "memory")
#define CP_WAIT0()   asm volatile("cp.async.wait_group 0;" ::: "memory")

#define CLUSTER_ARRIVE() asm volatile("barrier.cluster.arrive.aligned;" ::: "memory")
#define CLUSTER_WAIT()   asm volatile("barrier.cluster.wait.aligned;"   ::: "memory")

// ---------------------------------------------------------------------------
// tcgen05 helpers (only in the sm_103a feature pass)
// ---------------------------------------------------------------------------
#if HAS_TCGEN05
__device__ __forceinline__ uint32_t elect_one() {
    uint32_t p;
    asm volatile("{\n\t.reg .pred p;\n\telect.sync _|p, 0xFFFFFFFF;\n\tselp.b32 %0, 1, 0, p;\n\t}"
                 : "=r"(p));
    return p;
}

#define MBARRIER_INIT(addr, cnt) \
    asm volatile("mbarrier.init.shared.b64 [%0], %1;" :: "r"((uint32_t)(addr)), "r"((uint32_t)(cnt)) : "memory")

#define MBARRIER_WAIT_PARITY(addr, parity) do {                                              \
    uint32_t _m = (uint32_t)(addr); uint32_t _p = (uint32_t)(parity); uint32_t _d;            \
    asm volatile("{\n\t.reg .pred p;\n\t"                                                     \
        "mbarrier.try_wait.parity.acquire.cta.shared::cta.b64 p, [%1], %2;\n\t"               \
        "selp.b32 %0, 1, 0, p;\n\t}" : "=r"(_d) : "r"(_m), "r"(_p) : "memory");               \
    if (!_d) {                                                                                \
        asm volatile("{\n\t.reg .pred P1;\n\t"                                                \
            "WL_%=:\n\t"                                                                      \
            "mbarrier.try_wait.parity.acquire.cta.shared::cta.b64 P1, [%0], %1, 0x989680;\n\t"\
            "@P1 bra.uni WD_%=;\n\t"                                                          \
            "bra.uni WL_%=;\n\t"                                                              \
            "WD_%=:\n\t}" :: "r"(_m), "r"(_p) : "memory");                                    \
    }                                                                                         \
} while (0)

// arrive on the same-offset mbarrier in cluster CTA `rank`
#define MBARRIER_ARRIVE_CLUSTER(local_addr, rank) \
    asm volatile("{\n\t.reg .b32 r;\n\t" \
        "mapa.shared::cluster.u32 r, %0, %1;\n\t" \
        "mbarrier.arrive.release.cluster.shared::cluster.b64 _, [r];\n\t}" \
        :: "r"((uint32_t)(local_addr)), "r"((uint32_t)(rank)) : "memory")

#define TCGEN05_ALLOC_CG2(smem_addr, ncols) \
    asm volatile("tcgen05.alloc.cta_group::2.sync.aligned.shared::cta.b32 [%0], %1;" \
                 :: "r"((uint32_t)(smem_addr)), "r"((uint32_t)(ncols)) : "memory")
#define TCGEN05_DEALLOC_CG2(tmem, ncols) \
    asm volatile("tcgen05.dealloc.cta_group::2.sync.aligned.b32 %0, %1;" :: "r"(tmem), "r"((uint32_t)(ncols)))
#define TCGEN05_RELINQUISH_CG2() \
    asm volatile("tcgen05.relinquish_alloc_permit.cta_group::2.sync.aligned;")
#define TCGEN05_COMMIT_MC_CG2(mbar) \
    asm volatile("tcgen05.commit.cta_group::2.mbarrier::arrive::one.shared::cluster.multicast::cluster.b64 [%0], %1;" \
                 :: "r"((uint32_t)(mbar)), "h"((uint16_t)0x3) : "memory")
#define TCGEN05_FENCE_AFTER()  asm volatile("tcgen05.fence::after_thread_sync;"  ::: "memory")
#define TCGEN05_FENCE_BEFORE() asm volatile("tcgen05.fence::before_thread_sync;" ::: "memory")
#define TCGEN05_WAIT_LD()      asm volatile("tcgen05.wait::ld.sync.aligned;"     ::: "memory")
#define FENCE_PROXY_ASYNC()    asm volatile("fence.proxy.async.shared::cta;"     ::: "memory")

#define TCGEN05_LD_32X32B_X32(r, tmem_addr) \
    asm volatile( \
        "tcgen05.ld.sync.aligned.32x32b.x32.b32 " \
        "{%0, %1, %2, %3, %4, %5, %6, %7, " \
        " %8, %9, %10, %11, %12, %13, %14, %15, " \
        " %16, %17, %18, %19, %20, %21, %22, %23, " \
        " %24, %25, %26, %27, %28, %29, %30, %31}, [%32];" \
        : "=r"((r)[0]),  "=r"((r)[1]),  "=r"((r)[2]),  "=r"((r)[3]), \
          "=r"((r)[4]),  "=r"((r)[5]),  "=r"((r)[6]),  "=r"((r)[7]), \
          "=r"((r)[8]),  "=r"((r)[9]),  "=r"((r)[10]), "=r"((r)[11]), \
          "=r"((r)[12]), "=r"((r)[13]), "=r"((r)[14]), "=r"((r)[15]), \
          "=r"((r)[16]), "=r"((r)[17]), "=r"((r)[18]), "=r"((r)[19]), \
          "=r"((r)[20]), "=r"((r)[21]), "=r"((r)[22]), "=r"((r)[23]), \
          "=r"((r)[24]), "=r"((r)[25]), "=r"((r)[26]), "=r"((r)[27]), \
          "=r"((r)[28]), "=r"((r)[29]), "=r"((r)[30]), "=r"((r)[31]) \
        : "r"(tmem_addr))

__device__ __forceinline__ void mma_f16_ss_cg2(uint32_t d, uint64_t ad, uint64_t bd,
                                               uint32_t idesc, bool acc) {
    uint32_t en = acc ? 1u : 0u;
    asm volatile(
        "{\n\t.reg .pred p;\n\tsetp.ne.u32 p, %5, 0;\n\t"
        "tcgen05.mma.cta_group::2.kind::f16 [%0], %1, %2, %3, "
        "{%4, %4, %4, %4, %4, %4, %4, %4}, p;\n\t}"
        :: "r"(d), "l"(ad), "l"(bd), "r"(idesc), "r"(0u), "r"(en) : "memory");
}

__device__ __forceinline__ uint64_t make_desc(uint32_t addr) {
    const uint64_t base = (2ULL << 61) | (1ULL << 46) | (64ULL << 32) | (1ULL << 16);
    return base | ((uint64_t)(addr >> 4) & 0x3FFF);
}
// dtype=F32, a/b=BF16, N=256 (32<<17), M=256 (16<<24) for cta_group::2
#define MMA_IDESC_CG2 0x10400490u
#endif  // HAS_TCGEN05

// ---------------------------------------------------------------------------
// HMMA fallback helpers
// ---------------------------------------------------------------------------
__device__ __forceinline__ void ldsm4(uint32_t* r, uint32_t addr) {
    asm volatile("ldmatrix.sync.aligned.m8n8.x4.shared.b16 {%0,%1,%2,%3}, [%4];"
                 : "=r"(r[0]), "=r"(r[1]), "=r"(r[2]), "=r"(r[3]) : "r"(addr));
}

__device__ __forceinline__ void mma_bf16(float* d, const uint32_t* a, const uint32_t* b) {
    asm volatile(
        "mma.sync.aligned.m16n8k16.row.col.f32.bf16.bf16.f32 "
        "{%0,%1,%2,%3}, {%4,%5,%6,%7}, {%8,%9}, {%0,%1,%2,%3};"
        : "+f"(d[0]), "+f"(d[1]), "+f"(d[2]), "+f"(d[3])
        : "r"(a[0]), "r"(a[1]), "r"(a[2]), "r"(a[3]), "r"(b[0]), "r"(b[1]));
}

// ---------------------------------------------------------------------------
// GEMM: C[M,N] = (Ahi+Alo)[M,Kt] * (Bhi+Blo)[N,Kt]^T, fp32 out.
// 2-CTA cluster tile: M=256 (128/CTA) x N=256 (B split 128 rows/CTA).
// K chunk 64, double-buffered cp.async, cg2 tcgen05 MMA (hh+hl+lh).
// Grid: x = (N/256)*2 (cluster pairs), y = M/256, z = batch.
// ---------------------------------------------------------------------------
#define SM_TMEMPTR  0
#define SM_READY0   16
#define SM_READY1   24
#define SM_DONE0    32
#define SM_DONE1    40
#define SM_BUF      1024
#define STAGE_BYTES 65536          // Ahi 16K | Alo 16K | Bhi 16K | Blo 16K
#define GEMM_SMEM   (SM_BUF + 2 * STAGE_BYTES)

__global__ void __launch_bounds__(256, 1) __cluster_dims__(2, 1, 1)
gemm_split_kernel(const __nv_bfloat16* __restrict__ Ahi, const __nv_bfloat16* __restrict__ Alo,
                  const __nv_bfloat16* __restrict__ Bhi, const __nv_bfloat16* __restrict__ Blo,
                  float* __restrict__ C, int M, int N, int Ktot)
{
#if HAS_TCGEN05
    extern __shared__ char smem[];
    const uint32_t sb = smem_u32(smem);
    const int tid = threadIdx.x;
    const int wid = tid >> 5, lid = tid & 31;
    const int rank = (int)(blockIdx.x & 1);
    const int n0 = (int)(blockIdx.x >> 1) * 256;
    const int m0 = (int)blockIdx.y * 256;

    const size_t offA = (size_t)blockIdx.z * M * Ktot;
    const size_t offB = (size_t)blockIdx.z * N * Ktot;
    const __nv_bfloat16* pA[2] = { Ahi + offA, Alo + offA };
    const __nv_bfloat16* pB[2] = { Bhi + offB, Blo + offB };
    const int arow0 = m0 + rank * 128;       // this CTA's A rows
    const int brow0 = n0 + rank * 128;       // this CTA's B rows (N split)

    if (wid == 0) TCGEN05_ALLOC_CG2(sb + SM_TMEMPTR, 256);
    if (tid == 0) {
        MBARRIER_INIT(sb + SM_READY0, 2);
        MBARRIER_INIT(sb + SM_READY1, 2);
        MBARRIER_INIT(sb + SM_DONE0, 1);
        MBARRIER_INIT(sb + SM_DONE1, 1);
    }
    __syncthreads();
    uint32_t tmem;
    asm volatile("ld.shared.b32 %0, [%1];" : "=r"(tmem) : "r"(sb + SM_TMEMPTR));

    // both CTAs' barriers must be initialized before cross-CTA arrivals/commits
    CLUSTER_ARRIVE(); CLUSTER_WAIT();

    const int nchunks = Ktot >> 6;
    int dph[2] = {0, 0};
    int rph[2] = {0, 0};

    for (int c = 0; c < nchunks; c++) {
        const int buf = c & 1;
        const uint32_t stage = sb + SM_BUF + buf * STAGE_BYTES;
        if (c >= 2) {
            MBARRIER_WAIT_PARITY(sb + (buf ? SM_DONE1 : SM_DONE0), dph[buf]);
            dph[buf] ^= 1;
        }
        const int kt0 = c << 6;

        // A hi/lo: 128 rows x 128B each; B hi/lo halves: 128 rows x 128B each
#pragma unroll
        for (int s = 0; s < 2; s++) {
            const uint32_t dstA = stage + s * 16384;
            const uint32_t dstB = stage + 32768 + s * 16384;
#pragma unroll
            for (int j = 0; j < 4; j++) {
                const int idx = tid + j * 256;            // 0..1023
                const int row = idx >> 3, c16 = idx & 7;
                uint32_t off = (uint32_t)(row * 128 + c16 * 16);
                uint32_t sw = off ^ ((off >> 3) & 0x70);
                CP_ASYNC16(dstA + sw, pA[s] + (size_t)(arow0 + row) * Ktot + kt0 + c16 * 8);
                CP_ASYNC16(dstB + sw, pB[s] + (size_t)(brow0 + row) * Ktot + kt0 + c16 * 8);
            }
        }
        CP_COMMIT();
        CP_WAIT0();
        __syncthreads();
        FENCE_PROXY_ASYNC();
        if (tid == 0) MBARRIER_ARRIVE_CLUSTER(sb + (buf ? SM_READY1 : SM_READY0), 0);

        if (rank == 0 && wid == 0 && elect_one()) {
            MBARRIER_WAIT_PARITY(sb + (buf ? SM_READY1 : SM_READY0), rph[buf]);
            rph[buf] ^= 1;
            const uint64_t dAh = make_desc(stage + 0);
            const uint64_t dAl = make_desc(stage + 16384);
            const uint64_t dBh = make_desc(stage + 32768);
            const uint64_t dBl = make_desc(stage + 49152);
            const bool first = (c == 0);
#pragma unroll
            for (int s = 0; s < 4; s++)
                mma_f16_ss_cg2(tmem, dAh + s * 2, dBh + s * 2, MMA_IDESC_CG2, !(first && s == 0));
#pragma unroll
            for (int s = 0; s < 4; s++)
                mma_f16_ss_cg2(tmem, dAh + s * 2, dBl + s * 2, MMA_IDESC_CG2, true);
#pragma unroll
            for (int s = 0; s < 4; s++)
                mma_f16_ss_cg2(tmem, dAl + s * 2, dBh + s * 2, MMA_IDESC_CG2, true);
            TCGEN05_COMMIT_MC_CG2(sb + (buf ? SM_DONE1 : SM_DONE0));
        }
    }

    // drain both buffers' final commits
    MBARRIER_WAIT_PARITY(sb + SM_DONE0, dph[0]);
    MBARRIER_WAIT_PARITY(sb + SM_DONE1, dph[1]);
    TCGEN05_FENCE_AFTER();

    // epilogue: each CTA reads its own 128x256 from TMEM
    {
        const int sub = wid & 3, half = wid >> 2;
        const int row = sub * 32 + lid;
        float* crow = C + (size_t)blockIdx.z * M * N
                      + (size_t)(m0 + rank * 128 + row) * N + n0 + half * 128;
#pragma unroll
        for (int g = 0; g < 4; g++) {
            uint32_t regs[32];
            TCGEN05_LD_32X32B_X32(regs, tmem + half * 128 + g * 32);
            TCGEN05_WAIT_LD();
#pragma unroll
            for (int q = 0; q < 8; q++) {
                float4 f;
                f.x = __uint_as_float(regs[q * 4 + 0]);
                f.y = __uint_as_float(regs[q * 4 + 1]);
                f.z = __uint_as_float(regs[q * 4 + 2]);
                f.w = __uint_as_float(regs[q * 4 + 3]);
                *(float4*)(crow + g * 32 + q * 4) = f;
            }
        }
    }
    TCGEN05_FENCE_BEFORE();
    __syncthreads();
    if (wid == 0) {
        TCGEN05_RELINQUISH_CG2();
        TCGEN05_DEALLOC_CG2(tmem, 256);
    }
    CLUSTER_ARRIVE(); CLUSTER_WAIT();

#else
    // ===================== HMMA (mma.sync) fallback =====================
    extern __shared__ char smem[];
    const uint32_t sb = smem_u32(smem);
    const int tid  = threadIdx.x;
    const int lane = tid & 31, wid = tid >> 5;
    const int wm = wid & 1, wn = wid >> 1;
    const int m0 = (int)blockIdx.y * 256 + (int)(blockIdx.x & 1) * 128;

    const size_t offA = (size_t)blockIdx.z * M * Ktot;
    const size_t offB = (size_t)blockIdx.z * N * Ktot;
    const uint32_t mats[4] = { sb, sb + 10240u, sb + 20480u, sb + 30720u };

    const uint32_t a_off = (uint32_t)((wm * 64 + (lane & 15)) * 80 + (lane >> 4) * 16);
    const uint32_t b_off = (uint32_t)((wn * 32 + ((lane >> 4) & 1) * 8 + (lane & 7)) * 80
                                      + ((lane >> 3) & 1) * 16);
    const int lr = tid >> 2, lq = tid & 3;
    const int nchunks = Ktot >> 5;

    for (int h = 0; h < 2; h++) {
        const int n0 = (int)(blockIdx.x >> 1) * 256 + h * 128;
        const __nv_bfloat16* srcs[4] = { Ahi + offA, Alo + offA, Bhi + offB, Blo + offB };
        const int rb[4] = { m0, m0, n0, n0 };

        float acc[4][4][4];
#pragma unroll
        for (int i = 0; i < 4; i++)
#pragma unroll
            for (int j = 0; j < 4; j++)
#pragma unroll
                for (int q = 0; q < 4; q++) acc[i][j][q] = 0.0f;

        uint4 st[4][2];
#pragma unroll 1
        for (int c = 0; c < nchunks; c++) {
            if (c == 0) {
#pragma unroll
                for (int s = 0; s < 4; s++)
#pragma unroll
                    for (int j = 0; j < 2; j++)
                        st[s][j] = *(const uint4*)(srcs[s] + (size_t)(rb[s] + lr + j * 64) * Ktot + lq * 8);
            }
            __syncthreads();
#pragma unroll
            for (int s = 0; s < 4; s++)
#pragma unroll
                for (int j = 0; j < 2; j++)
                    sts128(mats[s] + (uint32_t)((lr + j * 64) * 80 + lq * 16), st[s][j]);
            __syncthreads();

            if (c + 1 < nchunks) {
                const int kt1 = (c + 1) << 5;
#pragma unroll
                for (int s = 0; s < 4; s++)
#pragma unroll
                    for (int j = 0; j < 2; j++)
                        st[s][j] = *(const uint4*)(srcs[s] + (size_t)(rb[s] + lr + j * 64) * Ktot + kt1 + lq * 8);
            }

#pragma unroll
            for (int kb = 0; kb < 2; kb++) {
                uint32_t Ah[4][4], Al[4][4], Bh[2][4], Bl[2][4];
#pragma unroll
                for (int mt = 0; mt < 4; mt++) {
                    ldsm4(Ah[mt], mats[0] + a_off + (uint32_t)(mt * 1280 + kb * 32));
                    ldsm4(Al[mt], mats[1] + a_off + (uint32_t)(mt * 1280 + kb * 32));
                }
#pragma unroll
                for (int t2 = 0; t2 < 2; t2++) {
                    ldsm4(Bh[t2], mats[2] + b_off + (uint32_t)(t2 * 1280 + kb * 32));
                    ldsm4(Bl[t2], mats[3] + b_off + (uint32_t)(t2 * 1280 + kb * 32));
                }
#pragma unroll
                for (int mt = 0; mt < 4; mt++)
#pragma unroll
                    for (int nt = 0; nt < 4; nt++) {
                        const uint32_t* bh = &Bh[nt >> 1][(nt & 1) * 2];
                        const uint32_t* bl = &Bl[nt >> 1][(nt & 1) * 2];
                        mma_bf16(acc[mt][nt], Ah[mt], bh);
                        mma_bf16(acc[mt][nt], Ah[mt], bl);
                        mma_bf16(acc[mt][nt], Al[mt], bh);
                    }
            }
        }

        float* Cb = C + (size_t)blockIdx.z * M * N;
#pragma unroll
        for (int mt = 0; mt < 4; mt++)
#pragma unroll
            for (int nt = 0; nt < 4; nt++) {
                const int row = m0 + wm * 64 + mt * 16 + (lane >> 2);
                const int col = n0 + wn * 32 + nt * 8 + (lane & 3) * 2;
                float2 v0 = { acc[mt][nt][0], acc[mt][nt][1] };
                float2 v1 = { acc[mt][nt][2], acc[mt][nt][3] };
                *(float2*)&Cb[(size_t)row * N + col]       = v0;
                *(float2*)&Cb[(size_t)(row + 8) * N + col] = v1;
            }
        __syncthreads();
    }
#endif
}

// ---------------------------------------------------------------------------
// Conversions
// ---------------------------------------------------------------------------
__global__ void __launch_bounds__(256)
convert_split_kernel(const float* __restrict__ in,
                     __nv_bfloat16* __restrict__ hi,
                     __nv_bfloat16* __restrict__ lo, size_t n4) {
    size_t i = (size_t)blockIdx.x * 256 + threadIdx.x;
    if (i >= n4) return;
    float4 v = *(const float4*)(in + i * 4);
    __nv_bfloat16 h0, h1, h2, h3, l0, l1, l2, l3;
    split_bf16(v.x, h0, l0); split_bf16(v.y, h1, l1);
    split_bf16(v.z, h2, l2); split_bf16(v.w, h3, l3);
    __nv_bfloat162* ph = (__nv_bfloat162*)(hi + i * 4);
    __nv_bfloat162* pl = (__nv_bfloat162*)(lo + i * 4);
    ph[0] = __nv_bfloat162(h0, h1); ph[1] = __nv_bfloat162(h2, h3);
    pl[0] = __nv_bfloat162(l0, l1); pl[1] = __nv_bfloat162(l2, l3);
}

// K: one read -> row-major hi/lo AND transposed hi/lo
__global__ void __launch_bounds__(256)
k_convert_kernel(const float* __restrict__ Kin,
                 __nv_bfloat16* __restrict__ Khi, __nv_bfloat16* __restrict__ Klo,
                 __nv_bfloat16* __restrict__ KThi, __nv_bfloat16* __restrict__ KTlo) {
    __shared__ float tile[32][33];
    int b = blockIdx.z;
    int t0 = blockIdx.x * 32, d0 = blockIdx.y * 32;
    int tx = threadIdx.x & 31, ty = threadIdx.x >> 5;
    const float* src = Kin + (size_t)b * TK * HD;
    __nv_bfloat16* kh = Khi + (size_t)b * TK * HD;
    __nv_bfloat16* kl = Klo + (size_t)b * TK * HD;
#pragma unroll
    for (int r = 0; r < 4; r++) {
        int t = t0 + ty + 8 * r;
        float v = src[(size_t)t * HD + d0 + tx];
        tile[ty + 8 * r][tx] = v;
        __nv_bfloat16 h, l; split_bf16(v, h, l);
        kh[(size_t)t * HD + d0 + tx] = h;
        kl[(size_t)t * HD + d0 + tx] = l;
    }
    __syncthreads();
    __nv_bfloat16* oh = KThi + (size_t)b * HD * TK;
    __nv_bfloat16* ol = KTlo + (size_t)b * HD * TK;
#pragma unroll
    for (int r = 0; r < 4; r++) {
        int d = d0 + ty + 8 * r, t = t0 + tx;
        float v = tile[tx][ty + 8 * r];
        __nv_bfloat16 h, l; split_bf16(v, h, l);
        oh[(size_t)d * TK + t] = h;
        ol[(size_t)d * TK + t] = l;
    }
}

// ---------------------------------------------------------------------------
// Row softmax over TK, fp32 in, bf16 hi/lo out
// ---------------------------------------------------------------------------
__global__ void __launch_bounds__(256)
softmax_kernel(const float* __restrict__ E,
               __nv_bfloat16* __restrict__ Phi, __nv_bfloat16* __restrict__ Plo)
{
    const size_t row = blockIdx.x;
    const float* e = E + row * (size_t)TK;
    const int tid = threadIdx.x;
    const int lane = tid & 31, warp = tid >> 5;
    __shared__ float red[32];

    float v[8];
    float m = -INFINITY;
#pragma unroll
    for (int i = 0; i < 8; i++) { v[i] = e[tid + i * 256]; m = fmaxf(m, v[i]); }
#pragma unroll
    for (int o = 16; o > 0; o >>= 1) m = fmaxf(m, __shfl_xor_sync(0xffffffffu, m, o));
    if (lane == 0) red[warp] = m;
    __syncthreads();
    if (warp == 0) {
        float t = red[lane & 7];
#pragma unroll
        for (int o = 4; o > 0; o >>= 1) t = fmaxf(t, __shfl_xor_sync(0xffffffffu, t, o));
        red[lane] = t;
    }
    __syncthreads();
    m = red[0];

    float s = 0.0f;
#pragma unroll
    for (int i = 0; i < 8; i++) { v[i] = __expf(v[i] - m); s += v[i]; }
#pragma unroll
    for (int o = 16; o > 0; o >>= 1) s += __shfl_xor_sync(0xffffffffu, s, o);
    __syncthreads();
    if (lane == 0) red[warp] = s;
    __syncthreads();
    if (warp == 0) {
        float t = red[lane & 7];
#pragma unroll
        for (int o = 4; o > 0; o >>= 1) t += __shfl_xor_sync(0xffffffffu, t, o);
        red[lane] = t;
    }
    __syncthreads();
    const float inv = 1.0f / red[0];

#pragma unroll
    for (int i = 0; i < 8; i++) {
        const float p = v[i] * inv;
        __nv_bfloat16 h, l; split_bf16(p, h, l);
        const size_t idx = row * (size_t)TK + tid + i * 256;
        Phi[idx] = h; Plo[idx] = l;
    }
}

// ---------------------------------------------------------------------------
extern "C" void kernel_launch(void* const* d_in, const int* in_sizes, int n_in,
                              void* d_out, int out_size)
{
    const float* Q  = (const float*)d_in[0];
    const float* Kt = (const float*)d_in[1];
    float* O = (float*)d_out;

    float *E; __nv_bfloat16 *Qhi, *Qlo, *Khi, *Klo, *KThi, *KTlo, *Phi, *Plo;
    cudaGetSymbolAddress((void**)&E,    g_E);
    cudaGetSymbolAddress((void**)&Qhi,  g_Qhi);
    cudaGetSymbolAddress((void**)&Qlo,  g_Qlo);
    cudaGetSymbolAddress((void**)&Khi,  g_Khi);
    cudaGetSymbolAddress((void**)&Klo,  g_Klo);
    cudaGetSymbolAddress((void**)&KThi, g_KThi);
    cudaGetSymbolAddress((void**)&KTlo, g_KTlo);
    cudaGetSymbolAddress((void**)&Phi,  g_Phi);
    cudaGetSymbolAddress((void**)&Plo,  g_Plo);

    cudaFuncSetAttribute(gemm_split_kernel,
                         cudaFuncAttributeMaxDynamicSharedMemorySize, GEMM_SMEM);

    {
        size_t n4 = (size_t)BATCH * TQ * HD / 4;
        convert_split_kernel<<<(unsigned)((n4 + 255) / 256), 256>>>(Q, Qhi, Qlo, n4);
    }
    {
        dim3 grid(TK / 32, HD / 32, BATCH);
        k_convert_kernel<<<grid, 256>>>(Kt, Khi, Klo, KThi, KTlo);
    }
    // GEMM1: E = Q K^T  (M=TQ, N=TK, Ktot=HD)
    {
        dim3 grid((TK / 256) * 2, TQ / 256, BATCH);
        gemm_split_kernel<<<grid, 256, GEMM_SMEM>>>(Qhi, Qlo, Khi, Klo, E, TQ, TK, HD);
    }
    softmax_kernel<<<BATCH * TQ, 256>>>(E, Phi, Plo);
    // GEMM2: O = P KT^T  (M=TQ, N=HD, Ktot=TK)
    {
        dim3 grid((HD / 256) * 2, TQ / 256, BATCH);
        gemm_split_kernel<<<grid, 256, GEMM_SMEM>>>(Phi, Plo, KThi, KTlo, O, TQ, HD, TK);
    }
    (void)in_sizes; (void)n_in; (void)out_size;
}

// round 8
// speedup vs baseline: 5.8535x; 1.0148x over previous
#include <cuda_runtime.h>
#include <cuda_bf16.h>
#include <cstdint>
#include <math.h>

#define BATCH 8
#define TQ    2048
#define TK    2048
#define HD    1024

#if defined(__CUDA_ARCH_FEAT_SM103_ALL) || defined(__CUDA_ARCH_FEAT_SM100_ALL)
#define HAS_TCGEN05 1
#else
#define HAS_TCGEN05 0
#endif

// ---------------------------------------------------------------------------
// Device scratch
// ---------------------------------------------------------------------------
__device__ float         g_E   [(size_t)BATCH * TQ * TK];
__device__ __nv_bfloat16 g_Qhi [(size_t)BATCH * TQ * HD];
__device__ __nv_bfloat16 g_Qlo [(size_t)BATCH * TQ * HD];
__device__ __nv_bfloat16 g_Khi [(size_t)BATCH * TK * HD];
__device__ __nv_bfloat16 g_Klo [(size_t)BATCH * TK * HD];
__device__ __nv_bfloat16 g_KThi[(size_t)BATCH * HD * TK];
__device__ __nv_bfloat16 g_KTlo[(size_t)BATCH * HD * TK];
__device__ __nv_bfloat16 g_Phi [(size_t)BATCH * TQ * TK];
__device__ __nv_bfloat16 g_Plo [(size_t)BATCH * TQ * TK];

// ---------------------------------------------------------------------------
// Common helpers
// ---------------------------------------------------------------------------
__device__ __forceinline__ uint32_t smem_u32(const void* p) {
    uint32_t a;
    asm("{ .reg .u64 t; cvta.to.shared.u64 t, %1; cvt.u32.u64 %0, t; }" : "=r"(a) : "l"(p));
    return a;
}

__device__ __forceinline__ void sts128(uint32_t addr, uint4 v) {
    asm volatile("st.shared.v4.b32 [%0], {%1,%2,%3,%4};"
                 :: "r"(addr), "r"(v.x), "r"(v.y), "r"(v.z), "r"(v.w) : "memory");
}

__device__ __forceinline__ void split_bf16(float x, __nv_bfloat16& h, __nv_bfloat16& l) {
    h = __float2bfloat16(x);
    l = __float2bfloat16(x - __bfloat162float(h));
}

#define CP_ASYNC16(dst, src) \
    asm volatile("cp.async.cg.shared.global [%0], [%1], 16;" :: "r"(dst), "l"(src) : "memory")
#define CP_COMMIT()  asm volatile("cp.async.commit_group;" ::: "memory")
#define CP_WAITG(n)  asm volatile("cp.async.wait_group %0;" :: "n"(n) : "memory")

#define CLUSTER_ARRIVE() asm volatile("barrier.cluster.arrive.aligned;" ::: "memory")
#define CLUSTER_WAIT()   asm volatile("barrier.cluster.wait.aligned;"   ::: "memory")

// ---------------------------------------------------------------------------
// tcgen05 helpers (only in the sm_103a feature pass)
// ---------------------------------------------------------------------------
#if HAS_TCGEN05
__device__ __forceinline__ uint32_t elect_one() {
    uint32_t p;
    asm volatile("{\n\t.reg .pred p;\n\telect.sync _|p, 0xFFFFFFFF;\n\tselp.b32 %0, 1, 0, p;\n\t}"
                 : "=r"(p));
    return p;
}

#define MBARRIER_INIT(addr, cnt) \
    asm volatile("mbarrier.init.shared.b64 [%0], %1;" :: "r"((uint32_t)(addr)), "r"((uint32_t)(cnt)) : "memory")

#define MBARRIER_WAIT_PARITY(addr, parity) do {                                              \
    uint32_t _m = (uint32_t)(addr); uint32_t _p = (uint32_t)(parity); uint32_t _d;            \
    asm volatile("{\n\t.reg .pred p;\n\t"                                                     \
        "mbarrier.try_wait.parity.acquire.cta.shared::cta.b64 p, [%1], %2;\n\t"               \
        "selp.b32 %0, 1, 0, p;\n\t}" : "=r"(_d) : "r"(_m), "r"(_p) : "memory");               \
    if (!_d) {                                                                                \
        asm volatile("{\n\t.reg .pred P1;\n\t"                                                \
            "WL_%=:\n\t"                                                                      \
            "mbarrier.try_wait.parity.acquire.cta.shared::cta.b64 P1, [%0], %1, 0x989680;\n\t"\
            "@P1 bra.uni WD_%=;\n\t"                                                          \
            "bra.uni WL_%=;\n\t"                                                              \
            "WD_%=:\n\t}" :: "r"(_m), "r"(_p) : "memory");                                    \
    }                                                                                         \
} while (0)

// arrive on the same-offset mbarrier in cluster CTA `rank`
#define MBARRIER_ARRIVE_CLUSTER(local_addr, rank) \
    asm volatile("{\n\t.reg .b32 r;\n\t" \
        "mapa.shared::cluster.u32 r, %0, %1;\n\t" \
        "mbarrier.arrive.release.cluster.shared::cluster.b64 _, [r];\n\t}" \
        :: "r"((uint32_t)(local_addr)), "r"((uint32_t)(rank)) : "memory")

#define TCGEN05_ALLOC_CG2(smem_addr, ncols) \
    asm volatile("tcgen05.alloc.cta_group::2.sync.aligned.shared::cta.b32 [%0], %1;" \
                 :: "r"((uint32_t)(smem_addr)), "r"((uint32_t)(ncols)) : "memory")
#define TCGEN05_DEALLOC_CG2(tmem, ncols) \
    asm volatile("tcgen05.dealloc.cta_group::2.sync.aligned.b32 %0, %1;" :: "r"(tmem), "r"((uint32_t)(ncols)))
#define TCGEN05_RELINQUISH_CG2() \
    asm volatile("tcgen05.relinquish_alloc_permit.cta_group::2.sync.aligned;")
#define TCGEN05_COMMIT_MC_CG2(mbar) \
    asm volatile("tcgen05.commit.cta_group::2.mbarrier::arrive::one.shared::cluster.multicast::cluster.b64 [%0], %1;" \
                 :: "r"((uint32_t)(mbar)), "h"((uint16_t)0x3) : "memory")
#define TCGEN05_FENCE_AFTER()  asm volatile("tcgen05.fence::after_thread_sync;"  ::: "memory")
#define TCGEN05_FENCE_BEFORE() asm volatile("tcgen05.fence::before_thread_sync;" ::: "memory")
#define TCGEN05_WAIT_LD()      asm volatile("tcgen05.wait::ld.sync.aligned;"     ::: "memory")
#define FENCE_PROXY_ASYNC()    asm volatile("fence.proxy.async.shared::cta;"     ::: "memory")

#define TCGEN05_LD_32X32B_X32(r, tmem_addr) \
    asm volatile( \
        "tcgen05.ld.sync.aligned.32x32b.x32.b32 " \
        "{%0, %1, %2, %3, %4, %5, %6, %7, " \
        " %8, %9, %10, %11, %12, %13, %14, %15, " \
        " %16, %17, %18, %19, %20, %21, %22, %23, " \
        " %24, %25, %26, %27, %28, %29, %30, %31}, [%32];" \
        : "=r"((r)[0]),  "=r"((r)[1]),  "=r"((r)[2]),  "=r"((r)[3]), \
          "=r"((r)[4]),  "=r"((r)[5]),  "=r"((r)[6]),  "=r"((r)[7]), \
          "=r"((r)[8]),  "=r"((r)[9]),  "=r"((r)[10]), "=r"((r)[11]), \
          "=r"((r)[12]), "=r"((r)[13]), "=r"((r)[14]), "=r"((r)[15]), \
          "=r"((r)[16]), "=r"((r)[17]), "=r"((r)[18]), "=r"((r)[19]), \
          "=r"((r)[20]), "=r"((r)[21]), "=r"((r)[22]), "=r"((r)[23]), \
          "=r"((r)[24]), "=r"((r)[25]), "=r"((r)[26]), "=r"((r)[27]), \
          "=r"((r)[28]), "=r"((r)[29]), "=r"((r)[30]), "=r"((r)[31]) \
        : "r"(tmem_addr))

__device__ __forceinline__ void mma_f16_ss_cg2(uint32_t d, uint64_t ad, uint64_t bd,
                                               uint32_t idesc, bool acc) {
    uint32_t en = acc ? 1u : 0u;
    asm volatile(
        "{\n\t.reg .pred p;\n\tsetp.ne.u32 p, %5, 0;\n\t"
        "tcgen05.mma.cta_group::2.kind::f16 [%0], %1, %2, %3, "
        "{%4, %4, %4, %4, %4, %4, %4, %4}, p;\n\t}"
        :: "r"(d), "l"(ad), "l"(bd), "r"(idesc), "r"(0u), "r"(en) : "memory");
}

__device__ __forceinline__ uint64_t make_desc(uint32_t addr) {
    const uint64_t base = (2ULL << 61) | (1ULL << 46) | (64ULL << 32) | (1ULL << 16);
    return base | ((uint64_t)(addr >> 4) & 0x3FFF);
}
// dtype=F32, a/b=BF16, N=256 (32<<17), M=256 (16<<24) for cta_group::2
#define MMA_IDESC_CG2 0x10400490u
#endif  // HAS_TCGEN05

// ---------------------------------------------------------------------------
// HMMA fallback helpers
// ---------------------------------------------------------------------------
__device__ __forceinline__ void ldsm4(uint32_t* r, uint32_t addr) {
    asm volatile("ldmatrix.sync.aligned.m8n8.x4.shared.b16 {%0,%1,%2,%3}, [%4];"
                 : "=r"(r[0]), "=r"(r[1]), "=r"(r[2]), "=r"(r[3]) : "r"(addr));
}

__device__ __forceinline__ void mma_bf16(float* d, const uint32_t* a, const uint32_t* b) {
    asm volatile(
        "mma.sync.aligned.m16n8k16.row.col.f32.bf16.bf16.f32 "
        "{%0,%1,%2,%3}, {%4,%5,%6,%7}, {%8,%9}, {%0,%1,%2,%3};"
        : "+f"(d[0]), "+f"(d[1]), "+f"(d[2]), "+f"(d[3])
        : "r"(a[0]), "r"(a[1]), "r"(a[2]), "r"(a[3]), "r"(b[0]), "r"(b[1]));
}

// ---------------------------------------------------------------------------
// GEMM: C[M,N] = (Ahi+Alo)[M,Kt] * (Bhi+Blo)[N,Kt]^T, fp32 out.
// 2-CTA cluster tile: M=256 (128/CTA) x N=256 (B split 128 rows/CTA).
// K chunk 64, 3-stage cp.async pipeline, cg2 tcgen05 MMA (hh+hl+lh).
// Grid: x = (N/256)*2 (cluster pairs), y = M/256, z = batch.
// ---------------------------------------------------------------------------
#define SM_TMEMPTR  0
#define SM_READY(b) (16 + 8 * (b))
#define SM_DONE(b)  (48 + 8 * (b))
#define SM_BUF      1024
#define STAGE_BYTES 65536          // Ahi 16K | Alo 16K | Bhi 16K | Blo 16K
#define NSTAGES     3
#define GEMM_SMEM   (SM_BUF + NSTAGES * STAGE_BYTES)

__global__ void __launch_bounds__(256, 1) __cluster_dims__(2, 1, 1)
gemm_split_kernel(const __nv_bfloat16* __restrict__ Ahi, const __nv_bfloat16* __restrict__ Alo,
                  const __nv_bfloat16* __restrict__ Bhi, const __nv_bfloat16* __restrict__ Blo,
                  float* __restrict__ C, int M, int N, int Ktot)
{
#if HAS_TCGEN05
    extern __shared__ char smem[];
    const uint32_t sb = smem_u32(smem);
    const int tid = threadIdx.x;
    const int wid = tid >> 5, lid = tid & 31;
    const int rank = (int)(blockIdx.x & 1);
    const int n0 = (int)(blockIdx.x >> 1) * 256;
    const int m0 = (int)blockIdx.y * 256;

    const size_t offA = (size_t)blockIdx.z * M * Ktot;
    const size_t offB = (size_t)blockIdx.z * N * Ktot;
    const __nv_bfloat16* pA[2] = { Ahi + offA, Alo + offA };
    const __nv_bfloat16* pB[2] = { Bhi + offB, Blo + offB };
    const int arow0 = m0 + rank * 128;       // this CTA's A rows
    const int brow0 = n0 + rank * 128;       // this CTA's B rows (N split)

    if (wid == 0) TCGEN05_ALLOC_CG2(sb + SM_TMEMPTR, 256);
    if (tid == 0) {
#pragma unroll
        for (int b = 0; b < NSTAGES; b++) {
            MBARRIER_INIT(sb + SM_READY(b), 2);
            MBARRIER_INIT(sb + SM_DONE(b), 1);
        }
    }
    __syncthreads();
    uint32_t tmem;
    asm volatile("ld.shared.b32 %0, [%1];" : "=r"(tmem) : "r"(sb + SM_TMEMPTR));

    // both CTAs' barriers must be initialized before cross-CTA arrivals/commits
    CLUSTER_ARRIVE(); CLUSTER_WAIT();

    const int nchunks = Ktot >> 6;

    // per-thread cp.async issue of one chunk into stage buffer
    auto issue_chunk = [&](int c, int buf) {
        const uint32_t stage = sb + SM_BUF + buf * STAGE_BYTES;
        const int kt0 = c << 6;
#pragma unroll
        for (int s = 0; s < 2; s++) {
            const uint32_t dstA = stage + s * 16384;
            const uint32_t dstB = stage + 32768 + s * 16384;
#pragma unroll
            for (int j = 0; j < 4; j++) {
                const int idx = tid + j * 256;            // 0..1023
                const int row = idx >> 3, c16 = idx & 7;
                uint32_t off = (uint32_t)(row * 128 + c16 * 16);
                uint32_t sw = off ^ ((off >> 3) & 0x70);
                CP_ASYNC16(dstA + sw, pA[s] + (size_t)(arow0 + row) * Ktot + kt0 + c16 * 8);
                CP_ASYNC16(dstB + sw, pB[s] + (size_t)(brow0 + row) * Ktot + kt0 + c16 * 8);
            }
        }
        CP_COMMIT();
    };

    int rph[NSTAGES] = {0, 0, 0};
    int dph[NSTAGES] = {0, 0, 0};

    // prologue: chunks 0 and 1 into buffers 0 and 1
    issue_chunk(0, 0);
    if (nchunks > 1) issue_chunk(1, 1);

    for (int c = 0; c < nchunks; c++) {
        const int buf = c % NSTAGES;
        // chunk c's group complete (chunk c+1's group may stay in flight)
        if (c + 1 < nchunks) { CP_WAITG(1); } else { CP_WAITG(0); }
        __syncthreads();
        FENCE_PROXY_ASYNC();
        if (tid == 0) MBARRIER_ARRIVE_CLUSTER(sb + SM_READY(buf), 0);

        if (rank == 0 && wid == 0 && elect_one()) {
            MBARRIER_WAIT_PARITY(sb + SM_READY(buf), rph[buf]);
            rph[buf] ^= 1;
            const uint32_t stage = sb + SM_BUF + buf * STAGE_BYTES;
            const uint64_t dAh = make_desc(stage + 0);
            const uint64_t dAl = make_desc(stage + 16384);
            const uint64_t dBh = make_desc(stage + 32768);
            const uint64_t dBl = make_desc(stage + 49152);
            const bool first = (c == 0);
#pragma unroll
            for (int s = 0; s < 4; s++)
                mma_f16_ss_cg2(tmem, dAh + s * 2, dBh + s * 2, MMA_IDESC_CG2, !(first && s == 0));
#pragma unroll
            for (int s = 0; s < 4; s++)
                mma_f16_ss_cg2(tmem, dAh + s * 2, dBl + s * 2, MMA_IDESC_CG2, true);
#pragma unroll
            for (int s = 0; s < 4; s++)
                mma_f16_ss_cg2(tmem, dAl + s * 2, dBh + s * 2, MMA_IDESC_CG2, true);
            TCGEN05_COMMIT_MC_CG2(sb + SM_DONE(buf));
        }

        // issue chunk c+2 into buffer (c+2)%3; its previous occupant is chunk c-1
        if (c + 2 < nchunks) {
            const int nb = (c + 2) % NSTAGES;
            if (c >= 1) {
                MBARRIER_WAIT_PARITY(sb + SM_DONE(nb), dph[nb]);
                dph[nb] ^= 1;
            }
            issue_chunk(c + 2, nb);
        }
    }

    // final commit covers all prior MMAs from the issuing thread
    {
        const int bl = (nchunks - 1) % NSTAGES;
        MBARRIER_WAIT_PARITY(sb + SM_DONE(bl), dph[bl]);
    }
    TCGEN05_FENCE_AFTER();

    // epilogue: each CTA reads its own 128x256 from TMEM
    {
        const int sub = wid & 3, half = wid >> 2;
        const int row = sub * 32 + lid;
        float* crow = C + (size_t)blockIdx.z * M * N
                      + (size_t)(m0 + rank * 128 + row) * N + n0 + half * 128;
#pragma unroll
        for (int g = 0; g < 4; g++) {
            uint32_t regs[32];
            TCGEN05_LD_32X32B_X32(regs, tmem + half * 128 + g * 32);
            TCGEN05_WAIT_LD();
#pragma unroll
            for (int q = 0; q < 8; q++) {
                float4 f;
                f.x = __uint_as_float(regs[q * 4 + 0]);
                f.y = __uint_as_float(regs[q * 4 + 1]);
                f.z = __uint_as_float(regs[q * 4 + 2]);
                f.w = __uint_as_float(regs[q * 4 + 3]);
                *(float4*)(crow + g * 32 + q * 4) = f;
            }
        }
    }
    TCGEN05_FENCE_BEFORE();
    __syncthreads();
    if (wid == 0) {
        TCGEN05_RELINQUISH_CG2();
        TCGEN05_DEALLOC_CG2(tmem, 256);
    }
    CLUSTER_ARRIVE(); CLUSTER_WAIT();

#else
    // ===================== HMMA (mma.sync) fallback =====================
    extern __shared__ char smem[];
    const uint32_t sb = smem_u32(smem);
    const int tid  = threadIdx.x;
    const int lane = tid & 31, wid = tid >> 5;
    const int wm = wid & 1, wn = wid >> 1;
    const int m0 = (int)blockIdx.y * 256 + (int)(blockIdx.x & 1) * 128;

    const size_t offA = (size_t)blockIdx.z * M * Ktot;
    const size_t offB = (size_t)blockIdx.z * N * Ktot;
    const uint32_t mats[4] = { sb, sb + 10240u, sb + 20480u, sb + 30720u };

    const uint32_t a_off = (uint32_t)((wm * 64 + (lane & 15)) * 80 + (lane >> 4) * 16);
    const uint32_t b_off = (uint32_t)((wn * 32 + ((lane >> 4) & 1) * 8 + (lane & 7)) * 80
                                      + ((lane >> 3) & 1) * 16);
    const int lr = tid >> 2, lq = tid & 3;
    const int nchunks = Ktot >> 5;

    for (int h = 0; h < 2; h++) {
        const int n0 = (int)(blockIdx.x >> 1) * 256 + h * 128;
        const __nv_bfloat16* srcs[4] = { Ahi + offA, Alo + offA, Bhi + offB, Blo + offB };
        const int rb[4] = { m0, m0, n0, n0 };

        float acc[4][4][4];
#pragma unroll
        for (int i = 0; i < 4; i++)
#pragma unroll
            for (int j = 0; j < 4; j++)
#pragma unroll
                for (int q = 0; q < 4; q++) acc[i][j][q] = 0.0f;

        uint4 st[4][2];
#pragma unroll 1
        for (int c = 0; c < nchunks; c++) {
            if (c == 0) {
#pragma unroll
                for (int s = 0; s < 4; s++)
#pragma unroll
                    for (int j = 0; j < 2; j++)
                        st[s][j] = *(const uint4*)(srcs[s] + (size_t)(rb[s] + lr + j * 64) * Ktot + lq * 8);
            }
            __syncthreads();
#pragma unroll
            for (int s = 0; s < 4; s++)
#pragma unroll
                for (int j = 0; j < 2; j++)
                    sts128(mats[s] + (uint32_t)((lr + j * 64) * 80 + lq * 16), st[s][j]);
            __syncthreads();

            if (c + 1 < nchunks) {
                const int kt1 = (c + 1) << 5;
#pragma unroll
                for (int s = 0; s < 4; s++)
#pragma unroll
                    for (int j = 0; j < 2; j++)
                        st[s][j] = *(const uint4*)(srcs[s] + (size_t)(rb[s] + lr + j * 64) * Ktot + kt1 + lq * 8);
            }

#pragma unroll
            for (int kb = 0; kb < 2; kb++) {
                uint32_t Ah[4][4], Al[4][4], Bh[2][4], Bl[2][4];
#pragma unroll
                for (int mt = 0; mt < 4; mt++) {
                    ldsm4(Ah[mt], mats[0] + a_off + (uint32_t)(mt * 1280 + kb * 32));
                    ldsm4(Al[mt], mats[1] + a_off + (uint32_t)(mt * 1280 + kb * 32));
                }
#pragma unroll
                for (int t2 = 0; t2 < 2; t2++) {
                    ldsm4(Bh[t2], mats[2] + b_off + (uint32_t)(t2 * 1280 + kb * 32));
                    ldsm4(Bl[t2], mats[3] + b_off + (uint32_t)(t2 * 1280 + kb * 32));
                }
#pragma unroll
                for (int mt = 0; mt < 4; mt++)
#pragma unroll
                    for (int nt = 0; nt < 4; nt++) {
                        const uint32_t* bh = &Bh[nt >> 1][(nt & 1) * 2];
                        const uint32_t* bl = &Bl[nt >> 1][(nt & 1) * 2];
                        mma_bf16(acc[mt][nt], Ah[mt], bh);
                        mma_bf16(acc[mt][nt], Ah[mt], bl);
                        mma_bf16(acc[mt][nt], Al[mt], bh);
                    }
            }
        }

        float* Cb = C + (size_t)blockIdx.z * M * N;
#pragma unroll
        for (int mt = 0; mt < 4; mt++)
#pragma unroll
            for (int nt = 0; nt < 4; nt++) {
                const int row = m0 + wm * 64 + mt * 16 + (lane >> 2);
                const int col = n0 + wn * 32 + nt * 8 + (lane & 3) * 2;
                float2 v0 = { acc[mt][nt][0], acc[mt][nt][1] };
                float2 v1 = { acc[mt][nt][2], acc[mt][nt][3] };
                *(float2*)&Cb[(size_t)row * N + col]       = v0;
                *(float2*)&Cb[(size_t)(row + 8) * N + col] = v1;
            }
        __syncthreads();
    }
#endif
}

// ---------------------------------------------------------------------------
// Conversions
// ---------------------------------------------------------------------------
__global__ void __launch_bounds__(256)
convert_split_kernel(const float* __restrict__ in,
                     __nv_bfloat16* __restrict__ hi,
                     __nv_bfloat16* __restrict__ lo, size_t n4) {
    size_t i = (size_t)blockIdx.x * 256 + threadIdx.x;
    if (i >= n4) return;
    float4 v = *(const float4*)(in + i * 4);
    __nv_bfloat16 h0, h1, h2, h3, l0, l1, l2, l3;
    split_bf16(v.x, h0, l0); split_bf16(v.y, h1, l1);
    split_bf16(v.z, h2, l2); split_bf16(v.w, h3, l3);
    __nv_bfloat162* ph = (__nv_bfloat162*)(hi + i * 4);
    __nv_bfloat162* pl = (__nv_bfloat162*)(lo + i * 4);
    ph[0] = __nv_bfloat162(h0, h1); ph[1] = __nv_bfloat162(h2, h3);
    pl[0] = __nv_bfloat162(l0, l1); pl[1] = __nv_bfloat162(l2, l3);
}

// K: one read -> row-major hi/lo AND transposed hi/lo
__global__ void __launch_bounds__(256)
k_convert_kernel(const float* __restrict__ Kin,
                 __nv_bfloat16* __restrict__ Khi, __nv_bfloat16* __restrict__ Klo,
                 __nv_bfloat16* __restrict__ KThi, __nv_bfloat16* __restrict__ KTlo) {
    __shared__ float tile[32][33];
    int b = blockIdx.z;
    int t0 = blockIdx.x * 32, d0 = blockIdx.y * 32;
    int tx = threadIdx.x & 31, ty = threadIdx.x >> 5;
    const float* src = Kin + (size_t)b * TK * HD;
    __nv_bfloat16* kh = Khi + (size_t)b * TK * HD;
    __nv_bfloat16* kl = Klo + (size_t)b * TK * HD;
#pragma unroll
    for (int r = 0; r < 4; r++) {
        int t = t0 + ty + 8 * r;
        float v = src[(size_t)t * HD + d0 + tx];
        tile[ty + 8 * r][tx] = v;
        __nv_bfloat16 h, l; split_bf16(v, h, l);
        kh[(size_t)t * HD + d0 + tx] = h;
        kl[(size_t)t * HD + d0 + tx] = l;
    }
    __syncthreads();
    __nv_bfloat16* oh = KThi + (size_t)b * HD * TK;
    __nv_bfloat16* ol = KTlo + (size_t)b * HD * TK;
#pragma unroll
    for (int r = 0; r < 4; r++) {
        int d = d0 + ty + 8 * r, t = t0 + tx;
        float v = tile[tx][ty + 8 * r];
        __nv_bfloat16 h, l; split_bf16(v, h, l);
        oh[(size_t)d * TK + t] = h;
        ol[(size_t)d * TK + t] = l;
    }
}

// ---------------------------------------------------------------------------
// Row softmax over TK, fp32 in, bf16 hi/lo out
// ---------------------------------------------------------------------------
__global__ void __launch_bounds__(256)
softmax_kernel(const float* __restrict__ E,
               __nv_bfloat16* __restrict__ Phi, __nv_bfloat16* __restrict__ Plo)
{
    const size_t row = blockIdx.x;
    const float* e = E + row * (size_t)TK;
    const int tid = threadIdx.x;
    const int lane = tid & 31, warp = tid >> 5;
    __shared__ float red[32];

    float v[8];
    float m = -INFINITY;
#pragma unroll
    for (int i = 0; i < 8; i++) { v[i] = e[tid + i * 256]; m = fmaxf(m, v[i]); }
#pragma unroll
    for (int o = 16; o > 0; o >>= 1) m = fmaxf(m, __shfl_xor_sync(0xffffffffu, m, o));
    if (lane == 0) red[warp] = m;
    __syncthreads();
    if (warp == 0) {
        float t = red[lane & 7];
#pragma unroll
        for (int o = 4; o > 0; o >>= 1) t = fmaxf(t, __shfl_xor_sync(0xffffffffu, t, o));
        red[lane] = t;
    }
    __syncthreads();
    m = red[0];

    float s = 0.0f;
#pragma unroll
    for (int i = 0; i < 8; i++) { v[i] = __expf(v[i] - m); s += v[i]; }
#pragma unroll
    for (int o = 16; o > 0; o >>= 1) s += __shfl_xor_sync(0xffffffffu, s, o);
    __syncthreads();
    if (lane == 0) red[warp] = s;
    __syncthreads();
    if (warp == 0) {
        float t = red[lane & 7];
#pragma unroll
        for (int o = 4; o > 0; o >>= 1) t += __shfl_xor_sync(0xffffffffu, t, o);
        red[lane] = t;
    }
    __syncthreads();
    const float inv = 1.0f / red[0];

#pragma unroll
    for (int i = 0; i < 8; i++) {
        const float p = v[i] * inv;
        __nv_bfloat16 h, l; split_bf16(p, h, l);
        const size_t idx = row * (size_t)TK + tid + i * 256;
        Phi[idx] = h; Plo[idx] = l;
    }
}

// ---------------------------------------------------------------------------
extern "C" void kernel_launch(void* const* d_in, const int* in_sizes, int n_in,
                              void* d_out, int out_size)
{
    const float* Q  = (const float*)d_in[0];
    const float* Kt = (const float*)d_in[1];
    float* O = (float*)d_out;

    float *E; __nv_bfloat16 *Qhi, *Qlo, *Khi, *Klo, *KThi, *KTlo, *Phi, *Plo;
    cudaGetSymbolAddress((void**)&E,    g_E);
    cudaGetSymbolAddress((void**)&Qhi,  g_Qhi);
    cudaGetSymbolAddress((void**)&Qlo,  g_Qlo);
    cudaGetSymbolAddress((void**)&Khi,  g_Khi);
    cudaGetSymbolAddress((void**)&Klo,  g_Klo);
    cudaGetSymbolAddress((void**)&KThi, g_KThi);
    cudaGetSymbolAddress((void**)&KTlo, g_KTlo);
    cudaGetSymbolAddress((void**)&Phi,  g_Phi);
    cudaGetSymbolAddress((void**)&Plo,  g_Plo);

    cudaFuncSetAttribute(gemm_split_kernel,
                         cudaFuncAttributeMaxDynamicSharedMemorySize, GEMM_SMEM);

    {
        size_t n4 = (size_t)BATCH * TQ * HD / 4;
        convert_split_kernel<<<(unsigned)((n4 + 255) / 256), 256>>>(Q, Qhi, Qlo, n4);
    }
    {
        dim3 grid(TK / 32, HD / 32, BATCH);
        k_convert_kernel<<<grid, 256>>>(Kt, Khi, Klo, KThi, KTlo);
    }
    // GEMM1: E = Q K^T  (M=TQ, N=TK, Ktot=HD)
    {
        dim3 grid((TK / 256) * 2, TQ / 256, BATCH);
        gemm_split_kernel<<<grid, 256, GEMM_SMEM>>>(Qhi, Qlo, Khi, Klo, E, TQ, TK, HD);
    }
    softmax_kernel<<<BATCH * TQ, 256>>>(E, Phi, Plo);
    // GEMM2: O = P KT^T  (M=TQ, N=HD, Ktot=TK)
    {
        dim3 grid((HD / 256) * 2, TQ / 256, BATCH);
        gemm_split_kernel<<<grid, 256, GEMM_SMEM>>>(Phi, Plo, KThi, KTlo, O, TQ, HD, TK);
    }
    (void)in_sizes; (void)n_in; (void)out_size;
}